// round 6
// baseline (speedup 1.0000x reference)
#include <cuda_runtime.h>
#include <cstdint>

// ---------------- problem constants ----------------
constexpr int B    = 8;
constexpr int C    = 5;
constexpr int NN   = 512;   // nodes
constexpr int FIN  = 768;
constexpr int H    = 4;
constexpr int DHID = 128;
constexpr int DOUT = 64;
constexpr int HD   = H * DHID;   // 512
constexpr int HD2  = H * DOUT;   // 256
constexpr int BC   = B * C;      // 40

// ---------------- scratch (device globals; no allocation allowed) ----------------
__device__ __align__(256) float g_feat[(size_t)BC * NN * HD];
__device__ __align__(256) float g_h   [(size_t)BC * NN * HD];
__device__ __align__(256) float g_out2[(size_t)BC * NN * HD2];
__device__ __align__(256) float g_el  [BC * H * NN];
__device__ __align__(256) float g_er  [BC * H * NN];

// ---------------- gemm smem geometry (raw f32 staging, padded pitches) ----------------
constexpr int AP = 20;
constexpr int BP = 136;
constexpr int A_STG = 128 * AP;
constexpr int B_STG = 16 * BP;
constexpr int STG   = A_STG + B_STG;
constexpr int GEMM_SMEM = 3 * STG * 4;

__device__ __forceinline__ uint32_t f2tf32(float f) {
    uint32_t u;
    asm("cvt.rna.tf32.f32 %0, %1;" : "=r"(u) : "f"(f));
    return u;
}

__device__ __forceinline__ void mma_tf32(float* d, const uint32_t* a, const uint32_t* b) {
    asm volatile(
        "mma.sync.aligned.m16n8k8.row.col.f32.tf32.tf32.f32 "
        "{%0,%1,%2,%3}, {%4,%5,%6,%7}, {%8,%9}, {%0,%1,%2,%3};\n"
        : "+f"(d[0]), "+f"(d[1]), "+f"(d[2]), "+f"(d[3])
        : "r"(a[0]), "r"(a[1]), "r"(a[2]), "r"(a[3]), "r"(b[0]), "r"(b[1]));
}

__device__ __forceinline__ void cp16(uint32_t smem_dst, const float* gsrc) {
    asm volatile("cp.async.ca.shared.global [%0], [%1], 16;\n"
                 :: "r"(smem_dst), "l"(gsrc));
}

// ---------------- tf32 tensor-core GEMM (unchanged from R5) ----------
__global__ __launch_bounds__(256) void gemm_tc(
    const float* __restrict__ A, const float* __restrict__ W,
    float* __restrict__ Co, int K, int Nn, size_t aSB, size_t aSC) {
    extern __shared__ float sm[];

    int bc = blockIdx.z;
    int b  = bc / C, c = bc % C;
    const float* Ab = A + (size_t)b * aSB + (size_t)c * aSC;
    const float* Wc = W + (size_t)c * K * Nn;
    float*       Cb = Co + (size_t)bc * NN * Nn;

    int m0 = blockIdx.y * 128, n0 = blockIdx.x * 128;
    int tid  = threadIdx.x;
    int lane = tid & 31, warp = tid >> 5;
    int wm = warp & 1, wn = warp >> 1;
    int gr = lane >> 2, tg = lane & 3;

    uint32_t smem_base = (uint32_t)__cvta_generic_to_shared(sm);

    int am0 = tid >> 2,          akq = (tid & 3) * 4;
    int am1 = (tid + 256) >> 2;
    int bk0 = tid >> 5,          bnq = (tid & 31) * 4;
    int bk1 = (tid + 256) >> 5;

    auto issue_stage = [&](int st, int t) {
        uint32_t aB = smem_base + (st * STG) * 4;
        uint32_t bB = smem_base + (st * STG + A_STG) * 4;
        const float* Abt = Ab + (size_t)m0 * K + t * 16;
        cp16(aB + (am0 * AP + akq) * 4, Abt + (size_t)am0 * K + akq);
        cp16(aB + (am1 * AP + akq) * 4, Abt + (size_t)am1 * K + akq);
        const float* Wct = Wc + (size_t)(t * 16) * Nn + n0;
        cp16(bB + (bk0 * BP + bnq) * 4, Wct + (size_t)bk0 * Nn + bnq);
        cp16(bB + (bk1 * BP + bnq) * 4, Wct + (size_t)bk1 * Nn + bnq);
    };

    float acc[4][4][4] = {};

    auto compute_stage = [&](int st) {
        const float* As = sm + st * STG;
        const float* Bs = As + A_STG;
#pragma unroll
        for (int ks = 0; ks < 16; ks += 8) {
            int kA = ks + tg;
            uint32_t ah[4][4], al[4][4], bh[4][2], bl[4][2];
#pragma unroll
            for (int mt = 0; mt < 4; mt++) {
                int m = wm * 64 + mt * 16 + gr;
                float v0 = As[m * AP + kA];
                float v1 = As[(m + 8) * AP + kA];
                float v2 = As[m * AP + kA + 4];
                float v3 = As[(m + 8) * AP + kA + 4];
                ah[mt][0] = f2tf32(v0); al[mt][0] = f2tf32(v0 - __uint_as_float(ah[mt][0]));
                ah[mt][1] = f2tf32(v1); al[mt][1] = f2tf32(v1 - __uint_as_float(ah[mt][1]));
                ah[mt][2] = f2tf32(v2); al[mt][2] = f2tf32(v2 - __uint_as_float(ah[mt][2]));
                ah[mt][3] = f2tf32(v3); al[mt][3] = f2tf32(v3 - __uint_as_float(ah[mt][3]));
            }
#pragma unroll
            for (int nt = 0; nt < 4; nt++) {
                int n = wn * 32 + nt * 8 + gr;
                float w0 = Bs[kA * BP + n];
                float w1 = Bs[(kA + 4) * BP + n];
                bh[nt][0] = f2tf32(w0); bl[nt][0] = f2tf32(w0 - __uint_as_float(bh[nt][0]));
                bh[nt][1] = f2tf32(w1); bl[nt][1] = f2tf32(w1 - __uint_as_float(bh[nt][1]));
            }
#pragma unroll
            for (int mt = 0; mt < 4; mt++)
#pragma unroll
                for (int nt = 0; nt < 4; nt++) {
                    mma_tf32(acc[mt][nt], ah[mt], bh[nt]);
                    mma_tf32(acc[mt][nt], al[mt], bh[nt]);
                    mma_tf32(acc[mt][nt], ah[mt], bl[nt]);
                }
        }
    };

    int T = K / 16;
    issue_stage(0, 0);
    asm volatile("cp.async.commit_group;\n" ::);
    issue_stage(1, 1);
    asm volatile("cp.async.commit_group;\n" ::);

    for (int i = 0; i < T; i++) {
        asm volatile("cp.async.wait_group 1;\n" ::);
        __syncthreads();
        if (i + 2 < T) issue_stage((i + 2) % 3, i + 2);
        asm volatile("cp.async.commit_group;\n" ::);
        compute_stage(i % 3);
    }

#pragma unroll
    for (int mt = 0; mt < 4; mt++) {
#pragma unroll
        for (int nt = 0; nt < 4; nt++) {
            int row = m0 + wm * 64 + mt * 16 + gr;
            int col = n0 + wn * 32 + nt * 8 + tg * 2;
            *(float2*)(Cb + (size_t)row * Nn + col) =
                make_float2(acc[mt][nt][0], acc[mt][nt][1]);
            *(float2*)(Cb + (size_t)(row + 8) * Nn + col) =
                make_float2(acc[mt][nt][2], acc[mt][nt][3]);
        }
    }
}

// ---------------- el/er ----------------
__global__ void elr_kernel(const float* __restrict__ feat,
                           const float* __restrict__ al,
                           const float* __restrict__ ar,
                           float* __restrict__ el, float* __restrict__ er, int D) {
    int bcn = blockIdx.x;
    int bc = bcn / NN, i = bcn % NN;
    int c = bc % C;
    int h = threadIdx.x >> 5, lane = threadIdx.x & 31;

    const float* f   = feat + (size_t)bcn * (H * D) + h * D;
    const float* alh = al + (size_t)(c * H + h) * D;
    const float* arh = ar + (size_t)(c * H + h) * D;

    float sl = 0.f, sr = 0.f;
    for (int d = lane; d < D; d += 32) {
        float v = f[d];
        sl = fmaf(v, alh[d], sl);
        sr = fmaf(v, arh[d], sr);
    }
#pragma unroll
    for (int o = 16; o; o >>= 1) {
        sl += __shfl_down_sync(0xffffffffu, sl, o);
        sr += __shfl_down_sync(0xffffffffu, sr, o);
    }
    if (lane == 0) {
        el[((size_t)bc * H + h) * NN + i] = sl;
        er[((size_t)bc * H + h) * NN + i] = sr;
    }
}

// ---------------- tensor-core fused softmax + aggregation ----------------
// out[j,d] = (1/s_j) * sum_i p[i,j] * feat[i,d]  as tf32 3-term MMA.
// Block = (bc, h, JT j-columns). Warp grid: (JT/64) in j  x  (D/32) in d.
// p-tile 16 x JT produced in smem each i-step; s accumulated on the fly.
template <int D, int JT, bool RELU>
__global__ __launch_bounds__(256) void agg_tc(
    const float* __restrict__ adj,
    const float* __restrict__ feat,
    const float* __restrict__ el,
    const float* __restrict__ er,
    const float* __restrict__ bias,
    float* __restrict__ out) {
    constexpr int PP = JT + 8;     // p pitch: (tg*8+gr+c) mod 32 distinct
    constexpr int FP = D + 8;      // f pitch: same property
    constexpr int WJ = JT / 64;    // warps along j
    constexpr int NSUB = 256 / JT; // i-sublayers per thread in p production

    __shared__ float el_s[NN];
    __shared__ float er_s[JT], m_s[JT], sc_s[JT];
    __shared__ float p_s[16 * PP];
    __shared__ float f_s[16 * FP];
    __shared__ float red[8];
    __shared__ float s_red[2][JT];

    int bc = blockIdx.z, h = blockIdx.y;
    int c = bc % C;
    int j0 = blockIdx.x * JT;
    int tid = threadIdx.x;
    int lane = tid & 31, warp = tid >> 5;
    int jm = warp % WJ, dn = warp / WJ;
    int gr = lane >> 2, tg = lane & 3;

    const float* adj_bc = adj + (size_t)bc * NN * NN;
    const float* elh = el + (size_t)(bc * H + h) * NN;
    const float* erh = er + (size_t)(bc * H + h) * NN;

    float e0 = elh[tid], e1 = elh[tid + 256];
    el_s[tid] = e0; el_s[tid + 256] = e1;
#pragma unroll
    for (int t = tid; t < JT; t += 256) er_s[t] = erh[j0 + t];

    // unmasked max of el (valid shift: leaky is monotone, alpha shift-invariant)
    float v = fmaxf(e0, e1);
#pragma unroll
    for (int o = 16; o; o >>= 1) v = fmaxf(v, __shfl_xor_sync(0xffffffffu, v, o));
    if (lane == 0) red[warp] = v;
    __syncthreads();
    if (tid == 0) {
        float m = red[0];
#pragma unroll
        for (int w = 1; w < 8; w++) m = fmaxf(m, red[w]);
        red[0] = m;
    }
    __syncthreads();
#pragma unroll
    for (int t = tid; t < JT; t += 256) {
        float e = red[0] + er_s[t];
        m_s[t] = e > 0.f ? e : 0.2f * e;
    }
    __syncthreads();

    int pj  = tid % JT;
    int pi0 = tid / JT;            // 0..NSUB-1

    float acc[4][4][4] = {};
    float s_priv = 0.f;

    for (int ib = 0; ib < NN; ib += 16) {
        // ---- stage feat tile (16 x D) ----
#pragma unroll
        for (int l = 0; l < (16 * D / 4) / 256; l++) {
            int s = tid + l * 256;
            int r = s / (D / 4), cq = s % (D / 4);
            float4 fv4 = *(const float4*)(feat + ((size_t)bc * NN + ib + r) * (H * D) + h * D + cq * 4);
            *(float4*)&f_s[r * FP + cq * 4] = fv4;
        }
        // ---- produce p tile (16 x JT), accumulate s ----
#pragma unroll
        for (int q = 0; q < 16 / NSUB; q++) {
            int i = pi0 + q * NSUB;
            float a = adj_bc[(size_t)(ib + i) * NN + j0 + pj];
            float p = 0.f;
            if (a > 0.f) {
                float e = el_s[ib + i] + er_s[pj];
                e = e > 0.f ? e : 0.2f * e;
                p = __expf(e - m_s[pj]);
                s_priv += p;
            }
            p_s[i * PP + pj] = p;
        }
        __syncthreads();

        // ---- MMA: 64j x 32d per warp, k=16 in two ks-steps, 3-term split ----
#pragma unroll
        for (int ks = 0; ks < 16; ks += 8) {
            int kA = ks + tg;
            uint32_t ah[4][4], al4[4][4];
#pragma unroll
            for (int mt = 0; mt < 4; mt++) {
                int jb = jm * 64 + mt * 16 + gr;
                float v0 = p_s[kA * PP + jb];
                float v1 = p_s[kA * PP + jb + 8];
                float v2 = p_s[(kA + 4) * PP + jb];
                float v3 = p_s[(kA + 4) * PP + jb + 8];
                ah[mt][0] = f2tf32(v0); al4[mt][0] = f2tf32(v0 - __uint_as_float(ah[mt][0]));
                ah[mt][1] = f2tf32(v1); al4[mt][1] = f2tf32(v1 - __uint_as_float(ah[mt][1]));
                ah[mt][2] = f2tf32(v2); al4[mt][2] = f2tf32(v2 - __uint_as_float(ah[mt][2]));
                ah[mt][3] = f2tf32(v3); al4[mt][3] = f2tf32(v3 - __uint_as_float(ah[mt][3]));
            }
#pragma unroll
            for (int nt = 0; nt < 4; nt++) {
                int db = dn * 32 + nt * 8 + gr;
                float w0 = f_s[kA * FP + db];
                float w1 = f_s[(kA + 4) * FP + db];
                uint32_t bh[2], bl[2];
                bh[0] = f2tf32(w0); bl[0] = f2tf32(w0 - __uint_as_float(bh[0]));
                bh[1] = f2tf32(w1); bl[1] = f2tf32(w1 - __uint_as_float(bh[1]));
#pragma unroll
                for (int mt = 0; mt < 4; mt++) {
                    mma_tf32(acc[mt][nt], ah[mt], bh);
                    mma_tf32(acc[mt][nt], al4[mt], bh);
                    mma_tf32(acc[mt][nt], ah[mt], bl);
                }
            }
        }
        __syncthreads();
    }

    // ---- reduce s, scale, bias, (relu), store ----
    s_red[pi0][pj] = s_priv;
    if (NSUB == 1) s_red[1][pj] = 0.f;
    __syncthreads();
#pragma unroll
    for (int t = tid; t < JT; t += 256)
        sc_s[t] = 1.0f / fmaxf(s_red[0][t] + s_red[1][t], 1e-9f);
    __syncthreads();

    const float* bh_ = bias + (size_t)c * (H * D) + h * D;
#pragma unroll
    for (int mt = 0; mt < 4; mt++) {
#pragma unroll
        for (int nt = 0; nt < 4; nt++) {
            int jl = jm * 64 + mt * 16 + gr;
            int d  = dn * 32 + nt * 8 + tg * 2;
            float bb0 = bh_[d], bb1 = bh_[d + 1];
            float sc0 = sc_s[jl], sc1 = sc_s[jl + 8];
            float o0 = acc[mt][nt][0] * sc0 + bb0;
            float o1 = acc[mt][nt][1] * sc0 + bb1;
            float o2 = acc[mt][nt][2] * sc1 + bb0;
            float o3 = acc[mt][nt][3] * sc1 + bb1;
            if (RELU) {
                o0 = fmaxf(o0, 0.f); o1 = fmaxf(o1, 0.f);
                o2 = fmaxf(o2, 0.f); o3 = fmaxf(o3, 0.f);
            }
            int j = j0 + jl;
            *(float2*)(out + ((size_t)bc * NN + j) * (H * D) + h * D + d)     = make_float2(o0, o1);
            *(float2*)(out + ((size_t)bc * NN + j + 8) * (H * D) + h * D + d) = make_float2(o2, o3);
        }
    }
}

// ---------------- head-mean + channel concat ----------------
__global__ void mean_kernel(const float* __restrict__ in2, float* __restrict__ out) {
    int idx = blockIdx.x * 256 + threadIdx.x;
    if (idx >= B * NN * C * DOUT) return;
    int d = idx % DOUT;
    int c = (idx / DOUT) % C;
    int n = (idx / (DOUT * C)) % NN;
    int b = idx / (DOUT * C * NN);
    const float* p = in2 + ((size_t)(b * C + c) * NN + n) * HD2 + d;
    out[idx] = 0.25f * (p[0] + p[DOUT] + p[2 * DOUT] + p[3 * DOUT]);
}

// ---------------- launch ----------------
extern "C" void kernel_launch(void* const* d_in, const int* in_sizes, int n_in,
                              void* d_out, int out_size) {
    const float* x   = (const float*)d_in[0];
    const float* adj = (const float*)d_in[1];
    const float* W0  = (const float*)d_in[2];
    const float* al0 = (const float*)d_in[3];
    const float* ar0 = (const float*)d_in[4];
    const float* b0  = (const float*)d_in[5];
    const float* W1  = (const float*)d_in[6];
    const float* al1 = (const float*)d_in[7];
    const float* ar1 = (const float*)d_in[8];
    const float* b1  = (const float*)d_in[9];
    const float* W2  = (const float*)d_in[10];
    const float* al2 = (const float*)d_in[11];
    const float* ar2 = (const float*)d_in[12];
    const float* b2  = (const float*)d_in[13];
    float* out = (float*)d_out;

    float *feat, *hbuf, *el, *er, *out2;
    cudaGetSymbolAddress((void**)&feat, g_feat);
    cudaGetSymbolAddress((void**)&hbuf, g_h);
    cudaGetSymbolAddress((void**)&el,   g_el);
    cudaGetSymbolAddress((void**)&er,   g_er);
    cudaGetSymbolAddress((void**)&out2, g_out2);

    dim3 t256(256);
    static int attr_set = 0;
    if (!attr_set) {
        cudaFuncSetAttribute(gemm_tc, cudaFuncAttributeMaxDynamicSharedMemorySize, GEMM_SMEM);
        attr_set = 1;
    }

    // ---- layer 0 ----
    gemm_tc<<<dim3(HD / 128, NN / 128, BC), t256, GEMM_SMEM>>>(x, W0, feat, FIN, HD,
                                                               (size_t)C * NN * FIN, 0);
    elr_kernel<<<BC * NN, 128>>>(feat, al0, ar0, el, er, DHID);
    agg_tc<DHID, 128, true><<<dim3(NN / 128, H, BC), t256>>>(adj, feat, el, er, b0, hbuf);

    // ---- layer 1 ----
    gemm_tc<<<dim3(HD / 128, NN / 128, BC), t256, GEMM_SMEM>>>(hbuf, W1, feat, HD, HD,
                                                               (size_t)C * NN * HD, (size_t)NN * HD);
    elr_kernel<<<BC * NN, 128>>>(feat, al1, ar1, el, er, DHID);
    agg_tc<DHID, 128, true><<<dim3(NN / 128, H, BC), t256>>>(adj, feat, el, er, b1, hbuf);

    // ---- layer 2 ----
    gemm_tc<<<dim3(HD2 / 128, NN / 128, BC), t256, GEMM_SMEM>>>(hbuf, W2, feat, HD, HD2,
                                                                (size_t)C * NN * HD, (size_t)NN * HD);
    elr_kernel<<<BC * NN, 128>>>(feat, al2, ar2, el, er, DOUT);
    agg_tc<DOUT, 256, false><<<dim3(NN / 256, H, BC), t256>>>(adj, feat, el, er, b2, out2);

    // ---- head mean + concat ----
    mean_kernel<<<(B * NN * C * DOUT + 255) / 256, t256>>>(out2, out);
}

// round 7
// speedup vs baseline: 1.4301x; 1.4301x over previous
#include <cuda_runtime.h>
#include <cstdint>

// ---------------- problem constants ----------------
constexpr int B    = 8;
constexpr int C    = 5;
constexpr int NN   = 512;   // nodes
constexpr int FIN  = 768;
constexpr int H    = 4;
constexpr int DHID = 128;
constexpr int DOUT = 64;
constexpr int HD   = H * DHID;   // 512
constexpr int HD2  = H * DOUT;   // 256
constexpr int BC   = B * C;      // 40

// ---------------- scratch (device globals; no allocation allowed) ----------------
__device__ __align__(256) float g_feat[(size_t)BC * NN * HD];
__device__ __align__(256) float g_h   [(size_t)BC * NN * HD];
__device__ __align__(256) float g_out2[(size_t)BC * NN * HD2];
__device__ __align__(256) float g_el  [BC * H * NN];
__device__ __align__(256) float g_er  [BC * H * NN];

// ---------------- gemm smem geometry ----------------
constexpr int AP = 20;
constexpr int BP = 136;
constexpr int A_STG = 128 * AP;
constexpr int B_STG = 16 * BP;
constexpr int STG   = A_STG + B_STG;
constexpr int GEMM_SMEM = 3 * STG * 4;

__device__ __forceinline__ uint32_t f2tf32(float f) {
    uint32_t u;
    asm("cvt.rna.tf32.f32 %0, %1;" : "=r"(u) : "f"(f));
    return u;
}

__device__ __forceinline__ void mma_tf32(float* d, const uint32_t* a, const uint32_t* b) {
    asm volatile(
        "mma.sync.aligned.m16n8k8.row.col.f32.tf32.tf32.f32 "
        "{%0,%1,%2,%3}, {%4,%5,%6,%7}, {%8,%9}, {%0,%1,%2,%3};\n"
        : "+f"(d[0]), "+f"(d[1]), "+f"(d[2]), "+f"(d[3])
        : "r"(a[0]), "r"(a[1]), "r"(a[2]), "r"(a[3]), "r"(b[0]), "r"(b[1]));
}

__device__ __forceinline__ void cp16(uint32_t smem_dst, const float* gsrc) {
    asm volatile("cp.async.ca.shared.global [%0], [%1], 16;\n"
                 :: "r"(smem_dst), "l"(gsrc));
}

// ---------------- tf32 tensor-core GEMM (unchanged, validated R5) ----------
__global__ __launch_bounds__(256) void gemm_tc(
    const float* __restrict__ A, const float* __restrict__ W,
    float* __restrict__ Co, int K, int Nn, size_t aSB, size_t aSC) {
    extern __shared__ float sm[];

    int bc = blockIdx.z;
    int b  = bc / C, c = bc % C;
    const float* Ab = A + (size_t)b * aSB + (size_t)c * aSC;
    const float* Wc = W + (size_t)c * K * Nn;
    float*       Cb = Co + (size_t)bc * NN * Nn;

    int m0 = blockIdx.y * 128, n0 = blockIdx.x * 128;
    int tid  = threadIdx.x;
    int lane = tid & 31, warp = tid >> 5;
    int wm = warp & 1, wn = warp >> 1;
    int gr = lane >> 2, tg = lane & 3;

    uint32_t smem_base = (uint32_t)__cvta_generic_to_shared(sm);

    int am0 = tid >> 2,          akq = (tid & 3) * 4;
    int am1 = (tid + 256) >> 2;
    int bk0 = tid >> 5,          bnq = (tid & 31) * 4;
    int bk1 = (tid + 256) >> 5;

    auto issue_stage = [&](int st, int t) {
        uint32_t aB = smem_base + (st * STG) * 4;
        uint32_t bB = smem_base + (st * STG + A_STG) * 4;
        const float* Abt = Ab + (size_t)m0 * K + t * 16;
        cp16(aB + (am0 * AP + akq) * 4, Abt + (size_t)am0 * K + akq);
        cp16(aB + (am1 * AP + akq) * 4, Abt + (size_t)am1 * K + akq);
        const float* Wct = Wc + (size_t)(t * 16) * Nn + n0;
        cp16(bB + (bk0 * BP + bnq) * 4, Wct + (size_t)bk0 * Nn + bnq);
        cp16(bB + (bk1 * BP + bnq) * 4, Wct + (size_t)bk1 * Nn + bnq);
    };

    float acc[4][4][4] = {};

    auto compute_stage = [&](int st) {
        const float* As = sm + st * STG;
        const float* Bs = As + A_STG;
#pragma unroll
        for (int ks = 0; ks < 16; ks += 8) {
            int kA = ks + tg;
            uint32_t ah[4][4], al[4][4], bh[4][2], bl[4][2];
#pragma unroll
            for (int mt = 0; mt < 4; mt++) {
                int m = wm * 64 + mt * 16 + gr;
                float v0 = As[m * AP + kA];
                float v1 = As[(m + 8) * AP + kA];
                float v2 = As[m * AP + kA + 4];
                float v3 = As[(m + 8) * AP + kA + 4];
                ah[mt][0] = f2tf32(v0); al[mt][0] = f2tf32(v0 - __uint_as_float(ah[mt][0]));
                ah[mt][1] = f2tf32(v1); al[mt][1] = f2tf32(v1 - __uint_as_float(ah[mt][1]));
                ah[mt][2] = f2tf32(v2); al[mt][2] = f2tf32(v2 - __uint_as_float(ah[mt][2]));
                ah[mt][3] = f2tf32(v3); al[mt][3] = f2tf32(v3 - __uint_as_float(ah[mt][3]));
            }
#pragma unroll
            for (int nt = 0; nt < 4; nt++) {
                int n = wn * 32 + nt * 8 + gr;
                float w0 = Bs[kA * BP + n];
                float w1 = Bs[(kA + 4) * BP + n];
                bh[nt][0] = f2tf32(w0); bl[nt][0] = f2tf32(w0 - __uint_as_float(bh[nt][0]));
                bh[nt][1] = f2tf32(w1); bl[nt][1] = f2tf32(w1 - __uint_as_float(bh[nt][1]));
            }
#pragma unroll
            for (int mt = 0; mt < 4; mt++)
#pragma unroll
                for (int nt = 0; nt < 4; nt++) {
                    mma_tf32(acc[mt][nt], ah[mt], bh[nt]);
                    mma_tf32(acc[mt][nt], al[mt], bh[nt]);
                    mma_tf32(acc[mt][nt], ah[mt], bl[nt]);
                }
        }
    };

    int T = K / 16;
    issue_stage(0, 0);
    asm volatile("cp.async.commit_group;\n" ::);
    issue_stage(1, 1);
    asm volatile("cp.async.commit_group;\n" ::);

    for (int i = 0; i < T; i++) {
        asm volatile("cp.async.wait_group 1;\n" ::);
        __syncthreads();
        if (i + 2 < T) issue_stage((i + 2) % 3, i + 2);
        asm volatile("cp.async.commit_group;\n" ::);
        compute_stage(i % 3);
    }

#pragma unroll
    for (int mt = 0; mt < 4; mt++) {
#pragma unroll
        for (int nt = 0; nt < 4; nt++) {
            int row = m0 + wm * 64 + mt * 16 + gr;
            int col = n0 + wn * 32 + nt * 8 + tg * 2;
            *(float2*)(Cb + (size_t)row * Nn + col) =
                make_float2(acc[mt][nt][0], acc[mt][nt][1]);
            *(float2*)(Cb + (size_t)(row + 8) * Nn + col) =
                make_float2(acc[mt][nt][2], acc[mt][nt][3]);
        }
    }
}

// ---------------- el/er ----------------
__global__ void elr_kernel(const float* __restrict__ feat,
                           const float* __restrict__ al,
                           const float* __restrict__ ar,
                           float* __restrict__ el, float* __restrict__ er, int D) {
    int bcn = blockIdx.x;
    int bc = bcn / NN, i = bcn % NN;
    int c = bc % C;
    int h = threadIdx.x >> 5, lane = threadIdx.x & 31;

    const float* f   = feat + (size_t)bcn * (H * D) + h * D;
    const float* alh = al + (size_t)(c * H + h) * D;
    const float* arh = ar + (size_t)(c * H + h) * D;

    float sl = 0.f, sr = 0.f;
    for (int d = lane; d < D; d += 32) {
        float v = f[d];
        sl = fmaf(v, alh[d], sl);
        sr = fmaf(v, arh[d], sr);
    }
#pragma unroll
    for (int o = 16; o; o >>= 1) {
        sl += __shfl_down_sync(0xffffffffu, sl, o);
        sr += __shfl_down_sync(0xffffffffu, sr, o);
    }
    if (lane == 0) {
        el[((size_t)bc * H + h) * NN + i] = sl;
        er[((size_t)bc * H + h) * NN + i] = sr;
    }
}

// ---------------- tensor-core fused softmax + aggregation, cp.async pipelined ----------
// out[j,d] = (1/s_j) * sum_i p[i,j] * feat[i,d], tf32 3-term split MMA.
// 3-stage cp.async ring for adj(16xJT) + feat(16xD); double-buffered p tile.
template <int D, int JT, bool RELU>
__global__ __launch_bounds__(256) void agg_tc(
    const float* __restrict__ adj,
    const float* __restrict__ feat,
    const float* __restrict__ el,
    const float* __restrict__ er,
    const float* __restrict__ bias,
    float* __restrict__ out) {
    constexpr int PP = JT + 8;
    constexpr int FP = D + 8;
    constexpr int WJ = JT / 64;
    constexpr int NSUB = 256 / JT;
    constexpr int ADJ_ST = 16 * JT;
    constexpr int F_ST   = 16 * FP;
    constexpr int P_ST   = 16 * PP;

    extern __shared__ float sm[];
    float* el_s  = sm;                       // 512
    float* er_s  = el_s + NN;                // JT
    float* m_s   = er_s + JT;                // JT
    float* sc_s  = m_s + JT;                 // JT
    float* red   = sc_s + JT;                // 8
    float* s_red = red + 8;                  // NSUB*JT
    float* adj_s = s_red + NSUB * JT;        // 3*16*JT
    float* f_s   = adj_s + 3 * ADJ_ST;       // 3*16*FP
    float* p_s   = f_s + 3 * F_ST;           // 2*16*PP

    int bc = blockIdx.z, h = blockIdx.y;
    int c = bc % C;
    int j0 = blockIdx.x * JT;
    int tid = threadIdx.x;
    int lane = tid & 31, warp = tid >> 5;
    int jm = warp % WJ, dn = warp / WJ;
    int gr = lane >> 2, tg = lane & 3;

    const float* adj_bc = adj + (size_t)bc * NN * NN;
    const float* elh = el + (size_t)(bc * H + h) * NN;
    const float* erh = er + (size_t)(bc * H + h) * NN;
    const float* featb = feat + (size_t)bc * NN * (H * D) + h * D;

    uint32_t smem_u32 = (uint32_t)__cvta_generic_to_shared(sm);
    uint32_t adj_u32  = smem_u32 + (uint32_t)((adj_s - sm) * 4);
    uint32_t f_u32    = smem_u32 + (uint32_t)((f_s - sm) * 4);

    // ---- stage issue: adj rows [t*16, t*16+16) x JT cols + feat rows x D ----
    auto issue_stage = [&](int st, int t) {
        uint32_t aB = adj_u32 + st * ADJ_ST * 4;
#pragma unroll
        for (int l = 0; l < (16 * JT / 4) / 256; l++) {
            int s = tid + l * 256;
            int r = s / (JT / 4), cq = s % (JT / 4);
            cp16(aB + (r * JT + cq * 4) * 4,
                 adj_bc + (size_t)(t * 16 + r) * NN + j0 + cq * 4);
        }
        uint32_t fB = f_u32 + st * F_ST * 4;
#pragma unroll
        for (int l = 0; l < (16 * D / 4) / 256; l++) {
            int s = tid + l * 256;
            int r = s / (D / 4), cq = s % (D / 4);
            cp16(fB + (r * FP + cq * 4) * 4,
                 featb + (size_t)(t * 16 + r) * (H * D) + cq * 4);
        }
    };

    // ---- prologue: el/er loads + unmasked-max shift ----
    float e0 = elh[tid], e1 = elh[tid + 256];
    el_s[tid] = e0; el_s[tid + 256] = e1;
#pragma unroll
    for (int t = tid; t < JT; t += 256) er_s[t] = erh[j0 + t];

    issue_stage(0, 0);
    asm volatile("cp.async.commit_group;\n" ::);
    issue_stage(1, 1);
    asm volatile("cp.async.commit_group;\n" ::);

    float v = fmaxf(e0, e1);
#pragma unroll
    for (int o = 16; o; o >>= 1) v = fmaxf(v, __shfl_xor_sync(0xffffffffu, v, o));
    if (lane == 0) red[warp] = v;
    __syncthreads();
    if (tid == 0) {
        float m = red[0];
#pragma unroll
        for (int w = 1; w < 8; w++) m = fmaxf(m, red[w]);
        red[0] = m;
    }
    __syncthreads();
#pragma unroll
    for (int t = tid; t < JT; t += 256) {
        float e = red[0] + er_s[t];
        m_s[t] = e > 0.f ? e : 0.2f * e;
    }

    int pj  = tid % JT;
    int pi0 = tid / JT;

    float acc[4][4][4] = {};
    float s_priv = 0.f;

    constexpr int T = NN / 16;
    for (int i = 0; i < T; i++) {
        asm volatile("cp.async.wait_group 1;\n" ::);
        __syncthreads();

        // ---- produce p tile from smem adj ----
        const float* a_st = adj_s + (i % 3) * ADJ_ST;
        float* p_buf = p_s + (i & 1) * P_ST;
#pragma unroll
        for (int q = 0; q < 16 / NSUB; q++) {
            int r = pi0 + q * NSUB;
            float a = a_st[r * JT + pj];
            float p = 0.f;
            if (a > 0.f) {
                float e = el_s[i * 16 + r] + er_s[pj];
                e = e > 0.f ? e : 0.2f * e;
                p = __expf(e - m_s[pj]);
                s_priv += p;
            }
            p_buf[r * PP + pj] = p;
        }
        __syncthreads();

        // ---- MMA: 64j x 32d per warp, 2 ks, 3-term split ----
        const float* f_st = f_s + (i % 3) * F_ST;
#pragma unroll
        for (int ks = 0; ks < 16; ks += 8) {
            int kA = ks + tg;
            uint32_t ah[4][4], al4[4][4];
#pragma unroll
            for (int mt = 0; mt < 4; mt++) {
                int jb = jm * 64 + mt * 16 + gr;
                float v0 = p_buf[kA * PP + jb];
                float v1 = p_buf[kA * PP + jb + 8];
                float v2 = p_buf[(kA + 4) * PP + jb];
                float v3 = p_buf[(kA + 4) * PP + jb + 8];
                ah[mt][0] = f2tf32(v0); al4[mt][0] = f2tf32(v0 - __uint_as_float(ah[mt][0]));
                ah[mt][1] = f2tf32(v1); al4[mt][1] = f2tf32(v1 - __uint_as_float(ah[mt][1]));
                ah[mt][2] = f2tf32(v2); al4[mt][2] = f2tf32(v2 - __uint_as_float(ah[mt][2]));
                ah[mt][3] = f2tf32(v3); al4[mt][3] = f2tf32(v3 - __uint_as_float(ah[mt][3]));
            }
#pragma unroll
            for (int nt = 0; nt < 4; nt++) {
                int db = dn * 32 + nt * 8 + gr;
                float w0 = f_st[kA * FP + db];
                float w1 = f_st[(kA + 4) * FP + db];
                uint32_t bh[2], bl[2];
                bh[0] = f2tf32(w0); bl[0] = f2tf32(w0 - __uint_as_float(bh[0]));
                bh[1] = f2tf32(w1); bl[1] = f2tf32(w1 - __uint_as_float(bh[1]));
#pragma unroll
                for (int mt = 0; mt < 4; mt++) {
                    mma_tf32(acc[mt][nt], ah[mt], bh);
                    mma_tf32(acc[mt][nt], al4[mt], bh);
                    mma_tf32(acc[mt][nt], ah[mt], bl);
                }
            }
        }

        if (i + 2 < T) issue_stage((i + 2) % 3, i + 2);
        asm volatile("cp.async.commit_group;\n" ::);
    }

    // ---- reduce s, scale, bias, (relu), store ----
    s_red[pi0 * JT + pj] = s_priv;
    __syncthreads();
#pragma unroll
    for (int t = tid; t < JT; t += 256) {
        float sv = s_red[t];
        if (NSUB == 2) sv += s_red[JT + t];
        sc_s[t] = 1.0f / fmaxf(sv, 1e-9f);
    }
    __syncthreads();

    const float* bh_ = bias + (size_t)c * (H * D) + h * D;
#pragma unroll
    for (int mt = 0; mt < 4; mt++) {
#pragma unroll
        for (int nt = 0; nt < 4; nt++) {
            int jl = jm * 64 + mt * 16 + gr;
            int d  = dn * 32 + nt * 8 + tg * 2;
            float bb0 = bh_[d], bb1 = bh_[d + 1];
            float sc0 = sc_s[jl], sc1 = sc_s[jl + 8];
            float o0 = acc[mt][nt][0] * sc0 + bb0;
            float o1 = acc[mt][nt][1] * sc0 + bb1;
            float o2 = acc[mt][nt][2] * sc1 + bb0;
            float o3 = acc[mt][nt][3] * sc1 + bb1;
            if (RELU) {
                o0 = fmaxf(o0, 0.f); o1 = fmaxf(o1, 0.f);
                o2 = fmaxf(o2, 0.f); o3 = fmaxf(o3, 0.f);
            }
            int j = j0 + jl;
            *(float2*)(out + ((size_t)bc * NN + j) * (H * D) + h * D + d)     = make_float2(o0, o1);
            *(float2*)(out + ((size_t)bc * NN + j + 8) * (H * D) + h * D + d) = make_float2(o2, o3);
        }
    }
}

// smem bytes for agg_tc<D, JT>
constexpr int agg_smem_bytes(int D, int JT) {
    int FP = D + 8, PP = JT + 8, NSUB = 256 / JT;
    return (NN + 3 * JT + 8 + NSUB * JT + 3 * 16 * JT + 3 * 16 * FP + 2 * 16 * PP) * 4;
}
constexpr int AGG_SMEM_128 = agg_smem_bytes(128, 128);  // 72736 B
constexpr int AGG_SMEM_64  = agg_smem_bytes(64, 256);   // 102944 B

// ---------------- head-mean + channel concat ----------------
__global__ void mean_kernel(const float* __restrict__ in2, float* __restrict__ out) {
    int idx = blockIdx.x * 256 + threadIdx.x;
    if (idx >= B * NN * C * DOUT) return;
    int d = idx % DOUT;
    int c = (idx / DOUT) % C;
    int n = (idx / (DOUT * C)) % NN;
    int b = idx / (DOUT * C * NN);
    const float* p = in2 + ((size_t)(b * C + c) * NN + n) * HD2 + d;
    out[idx] = 0.25f * (p[0] + p[DOUT] + p[2 * DOUT] + p[3 * DOUT]);
}

// ---------------- launch ----------------
extern "C" void kernel_launch(void* const* d_in, const int* in_sizes, int n_in,
                              void* d_out, int out_size) {
    const float* x   = (const float*)d_in[0];
    const float* adj = (const float*)d_in[1];
    const float* W0  = (const float*)d_in[2];
    const float* al0 = (const float*)d_in[3];
    const float* ar0 = (const float*)d_in[4];
    const float* b0  = (const float*)d_in[5];
    const float* W1  = (const float*)d_in[6];
    const float* al1 = (const float*)d_in[7];
    const float* ar1 = (const float*)d_in[8];
    const float* b1  = (const float*)d_in[9];
    const float* W2  = (const float*)d_in[10];
    const float* al2 = (const float*)d_in[11];
    const float* ar2 = (const float*)d_in[12];
    const float* b2  = (const float*)d_in[13];
    float* out = (float*)d_out;

    float *feat, *hbuf, *el, *er, *out2;
    cudaGetSymbolAddress((void**)&feat, g_feat);
    cudaGetSymbolAddress((void**)&hbuf, g_h);
    cudaGetSymbolAddress((void**)&el,   g_el);
    cudaGetSymbolAddress((void**)&er,   g_er);
    cudaGetSymbolAddress((void**)&out2, g_out2);

    dim3 t256(256);
    static int attr_set = 0;
    if (!attr_set) {
        cudaFuncSetAttribute(gemm_tc, cudaFuncAttributeMaxDynamicSharedMemorySize, GEMM_SMEM);
        cudaFuncSetAttribute(agg_tc<DHID, 128, true>,
                             cudaFuncAttributeMaxDynamicSharedMemorySize, AGG_SMEM_128);
        cudaFuncSetAttribute(agg_tc<DOUT, 256, false>,
                             cudaFuncAttributeMaxDynamicSharedMemorySize, AGG_SMEM_64);
        attr_set = 1;
    }

    // ---- layer 0 ----
    gemm_tc<<<dim3(HD / 128, NN / 128, BC), t256, GEMM_SMEM>>>(x, W0, feat, FIN, HD,
                                                               (size_t)C * NN * FIN, 0);
    elr_kernel<<<BC * NN, 128>>>(feat, al0, ar0, el, er, DHID);
    agg_tc<DHID, 128, true><<<dim3(NN / 128, H, BC), t256, AGG_SMEM_128>>>(adj, feat, el, er, b0, hbuf);

    // ---- layer 1 ----
    gemm_tc<<<dim3(HD / 128, NN / 128, BC), t256, GEMM_SMEM>>>(hbuf, W1, feat, HD, HD,
                                                               (size_t)C * NN * HD, (size_t)NN * HD);
    elr_kernel<<<BC * NN, 128>>>(feat, al1, ar1, el, er, DHID);
    agg_tc<DHID, 128, true><<<dim3(NN / 128, H, BC), t256, AGG_SMEM_128>>>(adj, feat, el, er, b1, hbuf);

    // ---- layer 2 ----
    gemm_tc<<<dim3(HD2 / 128, NN / 128, BC), t256, GEMM_SMEM>>>(hbuf, W2, feat, HD, HD2,
                                                                (size_t)C * NN * HD, (size_t)NN * HD);
    elr_kernel<<<BC * NN, 128>>>(feat, al2, ar2, el, er, DOUT);
    agg_tc<DOUT, 256, false><<<dim3(NN / 256, H, BC), t256, AGG_SMEM_64>>>(adj, feat, el, er, b2, out2);

    // ---- head mean + concat ----
    mean_kernel<<<(B * NN * C * DOUT + 255) / 256, t256>>>(out2, out);
}

// round 8
// speedup vs baseline: 1.4845x; 1.0380x over previous
#include <cuda_runtime.h>
#include <cstdint>

// ---------------- problem constants ----------------
constexpr int B    = 8;
constexpr int C    = 5;
constexpr int NN   = 512;   // nodes
constexpr int FIN  = 768;
constexpr int H    = 4;
constexpr int DHID = 128;
constexpr int DOUT = 64;
constexpr int HD   = H * DHID;   // 512
constexpr int HD2  = H * DOUT;   // 256
constexpr int BC   = B * C;      // 40

// ---------------- scratch (device globals; no allocation allowed) ----------------
__device__ __align__(256) float g_feat[(size_t)BC * NN * HD];
__device__ __align__(256) float g_h   [(size_t)BC * NN * HD];
__device__ __align__(256) float g_out2[(size_t)BC * NN * HD2];
__device__ __align__(256) float g_el  [BC * H * NN];
__device__ __align__(256) float g_er  [BC * H * NN];

// ---------------- gemm smem geometry ----------------
constexpr int AP = 20;
constexpr int BP = 136;
constexpr int A_STG = 128 * AP;
constexpr int B_STG = 16 * BP;
constexpr int STG   = A_STG + B_STG;
constexpr int GEMM_SMEM = 3 * STG * 4;

__device__ __forceinline__ uint32_t f2tf32(float f) {
    uint32_t u;
    asm("cvt.rna.tf32.f32 %0, %1;" : "=r"(u) : "f"(f));
    return u;
}

__device__ __forceinline__ void mma_tf32(float* d, const uint32_t* a, const uint32_t* b) {
    asm volatile(
        "mma.sync.aligned.m16n8k8.row.col.f32.tf32.tf32.f32 "
        "{%0,%1,%2,%3}, {%4,%5,%6,%7}, {%8,%9}, {%0,%1,%2,%3};\n"
        : "+f"(d[0]), "+f"(d[1]), "+f"(d[2]), "+f"(d[3])
        : "r"(a[0]), "r"(a[1]), "r"(a[2]), "r"(a[3]), "r"(b[0]), "r"(b[1]));
}

__device__ __forceinline__ void cp16(uint32_t smem_dst, const float* gsrc) {
    asm volatile("cp.async.ca.shared.global [%0], [%1], 16;\n"
                 :: "r"(smem_dst), "l"(gsrc));
}

// ---------------- tf32 tensor-core GEMM (unchanged, validated R5) ----------
__global__ __launch_bounds__(256) void gemm_tc(
    const float* __restrict__ A, const float* __restrict__ W,
    float* __restrict__ Co, int K, int Nn, size_t aSB, size_t aSC) {
    extern __shared__ float sm[];

    int bc = blockIdx.z;
    int b  = bc / C, c = bc % C;
    const float* Ab = A + (size_t)b * aSB + (size_t)c * aSC;
    const float* Wc = W + (size_t)c * K * Nn;
    float*       Cb = Co + (size_t)bc * NN * Nn;

    int m0 = blockIdx.y * 128, n0 = blockIdx.x * 128;
    int tid  = threadIdx.x;
    int lane = tid & 31, warp = tid >> 5;
    int wm = warp & 1, wn = warp >> 1;
    int gr = lane >> 2, tg = lane & 3;

    uint32_t smem_base = (uint32_t)__cvta_generic_to_shared(sm);

    int am0 = tid >> 2,          akq = (tid & 3) * 4;
    int am1 = (tid + 256) >> 2;
    int bk0 = tid >> 5,          bnq = (tid & 31) * 4;
    int bk1 = (tid + 256) >> 5;

    auto issue_stage = [&](int st, int t) {
        uint32_t aB = smem_base + (st * STG) * 4;
        uint32_t bB = smem_base + (st * STG + A_STG) * 4;
        const float* Abt = Ab + (size_t)m0 * K + t * 16;
        cp16(aB + (am0 * AP + akq) * 4, Abt + (size_t)am0 * K + akq);
        cp16(aB + (am1 * AP + akq) * 4, Abt + (size_t)am1 * K + akq);
        const float* Wct = Wc + (size_t)(t * 16) * Nn + n0;
        cp16(bB + (bk0 * BP + bnq) * 4, Wct + (size_t)bk0 * Nn + bnq);
        cp16(bB + (bk1 * BP + bnq) * 4, Wct + (size_t)bk1 * Nn + bnq);
    };

    float acc[4][4][4] = {};

    auto compute_stage = [&](int st) {
        const float* As = sm + st * STG;
        const float* Bs = As + A_STG;
#pragma unroll
        for (int ks = 0; ks < 16; ks += 8) {
            int kA = ks + tg;
            uint32_t ah[4][4], al[4][4], bh[4][2], bl[4][2];
#pragma unroll
            for (int mt = 0; mt < 4; mt++) {
                int m = wm * 64 + mt * 16 + gr;
                float v0 = As[m * AP + kA];
                float v1 = As[(m + 8) * AP + kA];
                float v2 = As[m * AP + kA + 4];
                float v3 = As[(m + 8) * AP + kA + 4];
                ah[mt][0] = f2tf32(v0); al[mt][0] = f2tf32(v0 - __uint_as_float(ah[mt][0]));
                ah[mt][1] = f2tf32(v1); al[mt][1] = f2tf32(v1 - __uint_as_float(ah[mt][1]));
                ah[mt][2] = f2tf32(v2); al[mt][2] = f2tf32(v2 - __uint_as_float(ah[mt][2]));
                ah[mt][3] = f2tf32(v3); al[mt][3] = f2tf32(v3 - __uint_as_float(ah[mt][3]));
            }
#pragma unroll
            for (int nt = 0; nt < 4; nt++) {
                int n = wn * 32 + nt * 8 + gr;
                float w0 = Bs[kA * BP + n];
                float w1 = Bs[(kA + 4) * BP + n];
                bh[nt][0] = f2tf32(w0); bl[nt][0] = f2tf32(w0 - __uint_as_float(bh[nt][0]));
                bh[nt][1] = f2tf32(w1); bl[nt][1] = f2tf32(w1 - __uint_as_float(bh[nt][1]));
            }
#pragma unroll
            for (int mt = 0; mt < 4; mt++)
#pragma unroll
                for (int nt = 0; nt < 4; nt++) {
                    mma_tf32(acc[mt][nt], ah[mt], bh[nt]);
                    mma_tf32(acc[mt][nt], al[mt], bh[nt]);
                    mma_tf32(acc[mt][nt], ah[mt], bl[nt]);
                }
        }
    };

    int T = K / 16;
    issue_stage(0, 0);
    asm volatile("cp.async.commit_group;\n" ::);
    issue_stage(1, 1);
    asm volatile("cp.async.commit_group;\n" ::);

    for (int i = 0; i < T; i++) {
        asm volatile("cp.async.wait_group 1;\n" ::);
        __syncthreads();
        if (i + 2 < T) issue_stage((i + 2) % 3, i + 2);
        asm volatile("cp.async.commit_group;\n" ::);
        compute_stage(i % 3);
    }

#pragma unroll
    for (int mt = 0; mt < 4; mt++) {
#pragma unroll
        for (int nt = 0; nt < 4; nt++) {
            int row = m0 + wm * 64 + mt * 16 + gr;
            int col = n0 + wn * 32 + nt * 8 + tg * 2;
            *(float2*)(Cb + (size_t)row * Nn + col) =
                make_float2(acc[mt][nt][0], acc[mt][nt][1]);
            *(float2*)(Cb + (size_t)(row + 8) * Nn + col) =
                make_float2(acc[mt][nt][2], acc[mt][nt][3]);
        }
    }
}

// ---------------- el/er ----------------
__global__ void elr_kernel(const float* __restrict__ feat,
                           const float* __restrict__ al,
                           const float* __restrict__ ar,
                           float* __restrict__ el, float* __restrict__ er, int D) {
    int bcn = blockIdx.x;
    int bc = bcn / NN, i = bcn % NN;
    int c = bc % C;
    int h = threadIdx.x >> 5, lane = threadIdx.x & 31;

    const float* f   = feat + (size_t)bcn * (H * D) + h * D;
    const float* alh = al + (size_t)(c * H + h) * D;
    const float* arh = ar + (size_t)(c * H + h) * D;

    float sl = 0.f, sr = 0.f;
    for (int d = lane; d < D; d += 32) {
        float v = f[d];
        sl = fmaf(v, alh[d], sl);
        sr = fmaf(v, arh[d], sr);
    }
#pragma unroll
    for (int o = 16; o; o >>= 1) {
        sl += __shfl_down_sync(0xffffffffu, sl, o);
        sr += __shfl_down_sync(0xffffffffu, sr, o);
    }
    if (lane == 0) {
        el[((size_t)bc * H + h) * NN + i] = sl;
        er[((size_t)bc * H + h) * NN + i] = sr;
    }
}

// ================= agg v2 (D=128, JT=128): produce-ahead, 1 barrier/iter =================
// ring-4 adj/feat stages; p double-buffered; per iter: MMA(i) then produce p(i+1).
template <bool RELU>
__global__ __launch_bounds__(256, 2) void agg_tc2(
    const float* __restrict__ adj,
    const float* __restrict__ feat,
    const float* __restrict__ el,
    const float* __restrict__ er,
    const float* __restrict__ bias,
    float* __restrict__ out) {
    constexpr int D  = 128, JT = 128;
    constexpr int PP = JT + 8;
    constexpr int FP = D + 8;
    constexpr int NSUB = 256 / JT;       // 2
    constexpr int ADJ_ST = 16 * JT;
    constexpr int F_ST   = 16 * FP;
    constexpr int P_ST   = 16 * PP;
    constexpr int T = NN / 16;

    extern __shared__ float sm[];
    float* el_s  = sm;                    // 512
    float* er_s  = el_s + NN;             // JT
    float* m_s   = er_s + JT;             // JT
    float* sc_s  = m_s + JT;              // JT
    float* red   = sc_s + JT;             // 8
    float* s_red = red + 8;               // NSUB*JT
    float* adj_s = s_red + NSUB * JT;     // 4*ADJ_ST
    float* f_s   = adj_s + 4 * ADJ_ST;    // 4*F_ST
    float* p_s   = f_s + 4 * F_ST;        // 2*P_ST

    int bc = blockIdx.z, h = blockIdx.y;
    int c = bc % C;
    int j0 = blockIdx.x * JT;
    int tid = threadIdx.x;
    int lane = tid & 31, warp = tid >> 5;
    int jm = warp & 1, dn = warp >> 1;
    int gr = lane >> 2, tg = lane & 3;

    const float* adj_bc = adj + (size_t)bc * NN * NN;
    const float* elh = el + (size_t)(bc * H + h) * NN;
    const float* erh = er + (size_t)(bc * H + h) * NN;
    const float* featb = feat + (size_t)bc * NN * (H * D) + h * D;

    uint32_t smem_u32 = (uint32_t)__cvta_generic_to_shared(sm);
    uint32_t adj_u32  = smem_u32 + (uint32_t)((adj_s - sm) * 4);
    uint32_t f_u32    = smem_u32 + (uint32_t)((f_s - sm) * 4);

    auto issue_stage = [&](int st, int t) {
        uint32_t aB = adj_u32 + st * ADJ_ST * 4;
#pragma unroll
        for (int l = 0; l < (16 * JT / 4) / 256; l++) {
            int s = tid + l * 256;
            int r = s / (JT / 4), cq = s % (JT / 4);
            cp16(aB + (r * JT + cq * 4) * 4,
                 adj_bc + (size_t)(t * 16 + r) * NN + j0 + cq * 4);
        }
        uint32_t fB = f_u32 + st * F_ST * 4;
#pragma unroll
        for (int l = 0; l < (16 * D / 4) / 256; l++) {
            int s = tid + l * 256;
            int r = s / (D / 4), cq = s % (D / 4);
            cp16(fB + (r * FP + cq * 4) * 4,
                 featb + (size_t)(t * 16 + r) * (H * D) + cq * 4);
        }
    };

    // ---- prologue ----
    float e0 = elh[tid], e1 = elh[tid + 256];
    el_s[tid] = e0; el_s[tid + 256] = e1;
    if (tid < JT) er_s[tid] = erh[j0 + tid];

    issue_stage(0, 0);
    asm volatile("cp.async.commit_group;\n" ::);
    issue_stage(1, 1);
    asm volatile("cp.async.commit_group;\n" ::);
    issue_stage(2, 2);
    asm volatile("cp.async.commit_group;\n" ::);

    float v = fmaxf(e0, e1);
#pragma unroll
    for (int o = 16; o; o >>= 1) v = fmaxf(v, __shfl_xor_sync(0xffffffffu, v, o));
    if (lane == 0) red[warp] = v;
    __syncthreads();
    if (tid == 0) {
        float m = red[0];
#pragma unroll
        for (int w = 1; w < 8; w++) m = fmaxf(m, red[w]);
        red[0] = m;
    }
    __syncthreads();
    if (tid < JT) {
        float e = red[0] + er_s[tid];
        m_s[tid] = e > 0.f ? e : 0.2f * e;
    }

    int pj  = tid % JT;
    int pi0 = tid / JT;

    float s_priv = 0.f;

    // produce p(t) into p_s[t&1]
    auto produce = [&](int t) {
        const float* a_st = adj_s + (t % 4) * ADJ_ST;
        float* p_nb = p_s + (t & 1) * P_ST;
#pragma unroll
        for (int q = 0; q < 16 / NSUB; q++) {
            int r = pi0 + q * NSUB;
            float a = a_st[r * JT + pj];
            float p = 0.f;
            if (a > 0.f) {
                float e = el_s[t * 16 + r] + er_s[pj];
                e = e > 0.f ? e : 0.2f * e;
                p = __expf(e - m_s[pj]);
                s_priv += p;
            }
            p_nb[r * PP + pj] = p;
        }
    };

    asm volatile("cp.async.wait_group 2;\n" ::);   // tile 0 landed
    __syncthreads();                               // m_s + adj stage0 visible
    produce(0);

    float acc[4][4][4] = {};

    for (int i = 0; i < T; i++) {
        asm volatile("cp.async.wait_group 1;\n" ::);   // tiles <= i+1 landed
        __syncthreads();                                // p(i) visible; slot reuse safe

        // ---- MMA(i): 64j x 32d per warp, 2 ks, 3-term split ----
        const float* f_st  = f_s + (i % 4) * F_ST;
        const float* p_buf = p_s + (i & 1) * P_ST;
#pragma unroll
        for (int ks = 0; ks < 16; ks += 8) {
            int kA = ks + tg;
            uint32_t ah[4][4], al4[4][4];
#pragma unroll
            for (int mt = 0; mt < 4; mt++) {
                int jb = jm * 64 + mt * 16 + gr;
                float v0 = p_buf[kA * PP + jb];
                float v1 = p_buf[kA * PP + jb + 8];
                float v2 = p_buf[(kA + 4) * PP + jb];
                float v3 = p_buf[(kA + 4) * PP + jb + 8];
                ah[mt][0] = f2tf32(v0); al4[mt][0] = f2tf32(v0 - __uint_as_float(ah[mt][0]));
                ah[mt][1] = f2tf32(v1); al4[mt][1] = f2tf32(v1 - __uint_as_float(ah[mt][1]));
                ah[mt][2] = f2tf32(v2); al4[mt][2] = f2tf32(v2 - __uint_as_float(ah[mt][2]));
                ah[mt][3] = f2tf32(v3); al4[mt][3] = f2tf32(v3 - __uint_as_float(ah[mt][3]));
            }
#pragma unroll
            for (int nt = 0; nt < 4; nt++) {
                int db = dn * 32 + nt * 8 + gr;
                float w0 = f_st[kA * FP + db];
                float w1 = f_st[(kA + 4) * FP + db];
                uint32_t bh[2], bl[2];
                bh[0] = f2tf32(w0); bl[0] = f2tf32(w0 - __uint_as_float(bh[0]));
                bh[1] = f2tf32(w1); bl[1] = f2tf32(w1 - __uint_as_float(bh[1]));
#pragma unroll
                for (int mt = 0; mt < 4; mt++) {
                    mma_tf32(acc[mt][nt], ah[mt], bh);
                    mma_tf32(acc[mt][nt], al4[mt], bh);
                    mma_tf32(acc[mt][nt], ah[mt], bl);
                }
            }
        }

        // ---- produce p(i+1) (overlaps other warps' MMA) ----
        if (i + 1 < T) produce(i + 1);

        if (i + 3 < T) issue_stage((i + 3) % 4, i + 3);
        asm volatile("cp.async.commit_group;\n" ::);
    }

    // ---- reduce s, scale, bias, (relu), store ----
    s_red[pi0 * JT + pj] = s_priv;
    __syncthreads();
    if (tid < JT)
        sc_s[tid] = 1.0f / fmaxf(s_red[tid] + s_red[JT + tid], 1e-9f);
    __syncthreads();

    const float* bh_ = bias + (size_t)c * (H * D) + h * D;
#pragma unroll
    for (int mt = 0; mt < 4; mt++) {
#pragma unroll
        for (int nt = 0; nt < 4; nt++) {
            int jl = jm * 64 + mt * 16 + gr;
            int d  = dn * 32 + nt * 8 + tg * 2;
            float bb0 = bh_[d], bb1 = bh_[d + 1];
            float sc0 = sc_s[jl], sc1 = sc_s[jl + 8];
            float o0 = acc[mt][nt][0] * sc0 + bb0;
            float o1 = acc[mt][nt][1] * sc0 + bb1;
            float o2 = acc[mt][nt][2] * sc1 + bb0;
            float o3 = acc[mt][nt][3] * sc1 + bb1;
            if (RELU) {
                o0 = fmaxf(o0, 0.f); o1 = fmaxf(o1, 0.f);
                o2 = fmaxf(o2, 0.f); o3 = fmaxf(o3, 0.f);
            }
            int j = j0 + jl;
            *(float2*)(out + ((size_t)bc * NN + j) * (H * D) + h * D + d)     = make_float2(o0, o1);
            *(float2*)(out + ((size_t)bc * NN + j + 8) * (H * D) + h * D + d) = make_float2(o2, o3);
        }
    }
}

constexpr int AGG2_SMEM = (NN + 3 * 128 + 8 + 2 * 128 + 4 * 16 * 128 + 4 * 16 * 136 + 2 * 16 * 136) * 4; // 89632

// ================= agg v1 (R7, validated) — used for layer 2 (D=64, JT=256) =================
template <int D, int JT, bool RELU>
__global__ __launch_bounds__(256) void agg_tc(
    const float* __restrict__ adj,
    const float* __restrict__ feat,
    const float* __restrict__ el,
    const float* __restrict__ er,
    const float* __restrict__ bias,
    float* __restrict__ out) {
    constexpr int PP = JT + 8;
    constexpr int FP = D + 8;
    constexpr int WJ = JT / 64;
    constexpr int NSUB = 256 / JT;
    constexpr int ADJ_ST = 16 * JT;
    constexpr int F_ST   = 16 * FP;
    constexpr int P_ST   = 16 * PP;

    extern __shared__ float sm[];
    float* el_s  = sm;
    float* er_s  = el_s + NN;
    float* m_s   = er_s + JT;
    float* sc_s  = m_s + JT;
    float* red   = sc_s + JT;
    float* s_red = red + 8;
    float* adj_s = s_red + NSUB * JT;
    float* f_s   = adj_s + 3 * ADJ_ST;
    float* p_s   = f_s + 3 * F_ST;

    int bc = blockIdx.z, h = blockIdx.y;
    int c = bc % C;
    int j0 = blockIdx.x * JT;
    int tid = threadIdx.x;
    int lane = tid & 31, warp = tid >> 5;
    int jm = warp % WJ, dn = warp / WJ;
    int gr = lane >> 2, tg = lane & 3;

    const float* adj_bc = adj + (size_t)bc * NN * NN;
    const float* elh = el + (size_t)(bc * H + h) * NN;
    const float* erh = er + (size_t)(bc * H + h) * NN;
    const float* featb = feat + (size_t)bc * NN * (H * D) + h * D;

    uint32_t smem_u32 = (uint32_t)__cvta_generic_to_shared(sm);
    uint32_t adj_u32  = smem_u32 + (uint32_t)((adj_s - sm) * 4);
    uint32_t f_u32    = smem_u32 + (uint32_t)((f_s - sm) * 4);

    auto issue_stage = [&](int st, int t) {
        uint32_t aB = adj_u32 + st * ADJ_ST * 4;
#pragma unroll
        for (int l = 0; l < (16 * JT / 4) / 256; l++) {
            int s = tid + l * 256;
            int r = s / (JT / 4), cq = s % (JT / 4);
            cp16(aB + (r * JT + cq * 4) * 4,
                 adj_bc + (size_t)(t * 16 + r) * NN + j0 + cq * 4);
        }
        uint32_t fB = f_u32 + st * F_ST * 4;
#pragma unroll
        for (int l = 0; l < (16 * D / 4) / 256; l++) {
            int s = tid + l * 256;
            int r = s / (D / 4), cq = s % (D / 4);
            cp16(fB + (r * FP + cq * 4) * 4,
                 featb + (size_t)(t * 16 + r) * (H * D) + cq * 4);
        }
    };

    float e0 = elh[tid], e1 = elh[tid + 256];
    el_s[tid] = e0; el_s[tid + 256] = e1;
#pragma unroll
    for (int t = tid; t < JT; t += 256) er_s[t] = erh[j0 + t];

    issue_stage(0, 0);
    asm volatile("cp.async.commit_group;\n" ::);
    issue_stage(1, 1);
    asm volatile("cp.async.commit_group;\n" ::);

    float v = fmaxf(e0, e1);
#pragma unroll
    for (int o = 16; o; o >>= 1) v = fmaxf(v, __shfl_xor_sync(0xffffffffu, v, o));
    if (lane == 0) red[warp] = v;
    __syncthreads();
    if (tid == 0) {
        float m = red[0];
#pragma unroll
        for (int w = 1; w < 8; w++) m = fmaxf(m, red[w]);
        red[0] = m;
    }
    __syncthreads();
#pragma unroll
    for (int t = tid; t < JT; t += 256) {
        float e = red[0] + er_s[t];
        m_s[t] = e > 0.f ? e : 0.2f * e;
    }

    int pj  = tid % JT;
    int pi0 = tid / JT;

    float acc[4][4][4] = {};
    float s_priv = 0.f;

    constexpr int T = NN / 16;
    for (int i = 0; i < T; i++) {
        asm volatile("cp.async.wait_group 1;\n" ::);
        __syncthreads();

        const float* a_st = adj_s + (i % 3) * ADJ_ST;
        float* p_buf = p_s + (i & 1) * P_ST;
#pragma unroll
        for (int q = 0; q < 16 / NSUB; q++) {
            int r = pi0 + q * NSUB;
            float a = a_st[r * JT + pj];
            float p = 0.f;
            if (a > 0.f) {
                float e = el_s[i * 16 + r] + er_s[pj];
                e = e > 0.f ? e : 0.2f * e;
                p = __expf(e - m_s[pj]);
                s_priv += p;
            }
            p_buf[r * PP + pj] = p;
        }
        __syncthreads();

        const float* f_st = f_s + (i % 3) * F_ST;
#pragma unroll
        for (int ks = 0; ks < 16; ks += 8) {
            int kA = ks + tg;
            uint32_t ah[4][4], al4[4][4];
#pragma unroll
            for (int mt = 0; mt < 4; mt++) {
                int jb = jm * 64 + mt * 16 + gr;
                float v0 = p_buf[kA * PP + jb];
                float v1 = p_buf[kA * PP + jb + 8];
                float v2 = p_buf[(kA + 4) * PP + jb];
                float v3 = p_buf[(kA + 4) * PP + jb + 8];
                ah[mt][0] = f2tf32(v0); al4[mt][0] = f2tf32(v0 - __uint_as_float(ah[mt][0]));
                ah[mt][1] = f2tf32(v1); al4[mt][1] = f2tf32(v1 - __uint_as_float(ah[mt][1]));
                ah[mt][2] = f2tf32(v2); al4[mt][2] = f2tf32(v2 - __uint_as_float(ah[mt][2]));
                ah[mt][3] = f2tf32(v3); al4[mt][3] = f2tf32(v3 - __uint_as_float(ah[mt][3]));
            }
#pragma unroll
            for (int nt = 0; nt < 4; nt++) {
                int db = dn * 32 + nt * 8 + gr;
                float w0 = f_st[kA * FP + db];
                float w1 = f_st[(kA + 4) * FP + db];
                uint32_t bh[2], bl[2];
                bh[0] = f2tf32(w0); bl[0] = f2tf32(w0 - __uint_as_float(bh[0]));
                bh[1] = f2tf32(w1); bl[1] = f2tf32(w1 - __uint_as_float(bh[1]));
#pragma unroll
                for (int mt = 0; mt < 4; mt++) {
                    mma_tf32(acc[mt][nt], ah[mt], bh);
                    mma_tf32(acc[mt][nt], al4[mt], bh);
                    mma_tf32(acc[mt][nt], ah[mt], bl);
                }
            }
        }

        if (i + 2 < T) issue_stage((i + 2) % 3, i + 2);
        asm volatile("cp.async.commit_group;\n" ::);
    }

    s_red[pi0 * JT + pj] = s_priv;
    __syncthreads();
#pragma unroll
    for (int t = tid; t < JT; t += 256) {
        float sv = s_red[t];
        if (NSUB == 2) sv += s_red[JT + t];
        sc_s[t] = 1.0f / fmaxf(sv, 1e-9f);
    }
    __syncthreads();

    const float* bh_ = bias + (size_t)c * (H * D) + h * D;
#pragma unroll
    for (int mt = 0; mt < 4; mt++) {
#pragma unroll
        for (int nt = 0; nt < 4; nt++) {
            int jl = jm * 64 + mt * 16 + gr;
            int d  = dn * 32 + nt * 8 + tg * 2;
            float bb0 = bh_[d], bb1 = bh_[d + 1];
            float sc0 = sc_s[jl], sc1 = sc_s[jl + 8];
            float o0 = acc[mt][nt][0] * sc0 + bb0;
            float o1 = acc[mt][nt][1] * sc0 + bb1;
            float o2 = acc[mt][nt][2] * sc1 + bb0;
            float o3 = acc[mt][nt][3] * sc1 + bb1;
            if (RELU) {
                o0 = fmaxf(o0, 0.f); o1 = fmaxf(o1, 0.f);
                o2 = fmaxf(o2, 0.f); o3 = fmaxf(o3, 0.f);
            }
            int j = j0 + jl;
            *(float2*)(out + ((size_t)bc * NN + j) * (H * D) + h * D + d)     = make_float2(o0, o1);
            *(float2*)(out + ((size_t)bc * NN + j + 8) * (H * D) + h * D + d) = make_float2(o2, o3);
        }
    }
}

constexpr int agg_smem_bytes(int D, int JT) {
    int FP = D + 8, PP = JT + 8, NSUB = 256 / JT;
    return (NN + 3 * JT + 8 + NSUB * JT + 3 * 16 * JT + 3 * 16 * FP + 2 * 16 * PP) * 4;
}
constexpr int AGG_SMEM_64 = agg_smem_bytes(64, 256);

// ---------------- head-mean + channel concat ----------------
__global__ void mean_kernel(const float* __restrict__ in2, float* __restrict__ out) {
    int idx = blockIdx.x * 256 + threadIdx.x;
    if (idx >= B * NN * C * DOUT) return;
    int d = idx % DOUT;
    int c = (idx / DOUT) % C;
    int n = (idx / (DOUT * C)) % NN;
    int b = idx / (DOUT * C * NN);
    const float* p = in2 + ((size_t)(b * C + c) * NN + n) * HD2 + d;
    out[idx] = 0.25f * (p[0] + p[DOUT] + p[2 * DOUT] + p[3 * DOUT]);
}

// ---------------- launch ----------------
extern "C" void kernel_launch(void* const* d_in, const int* in_sizes, int n_in,
                              void* d_out, int out_size) {
    const float* x   = (const float*)d_in[0];
    const float* adj = (const float*)d_in[1];
    const float* W0  = (const float*)d_in[2];
    const float* al0 = (const float*)d_in[3];
    const float* ar0 = (const float*)d_in[4];
    const float* b0  = (const float*)d_in[5];
    const float* W1  = (const float*)d_in[6];
    const float* al1 = (const float*)d_in[7];
    const float* ar1 = (const float*)d_in[8];
    const float* b1  = (const float*)d_in[9];
    const float* W2  = (const float*)d_in[10];
    const float* al2 = (const float*)d_in[11];
    const float* ar2 = (const float*)d_in[12];
    const float* b2  = (const float*)d_in[13];
    float* out = (float*)d_out;

    float *feat, *hbuf, *el, *er, *out2;
    cudaGetSymbolAddress((void**)&feat, g_feat);
    cudaGetSymbolAddress((void**)&hbuf, g_h);
    cudaGetSymbolAddress((void**)&el,   g_el);
    cudaGetSymbolAddress((void**)&er,   g_er);
    cudaGetSymbolAddress((void**)&out2, g_out2);

    dim3 t256(256);
    static int attr_set = 0;
    if (!attr_set) {
        cudaFuncSetAttribute(gemm_tc, cudaFuncAttributeMaxDynamicSharedMemorySize, GEMM_SMEM);
        cudaFuncSetAttribute(agg_tc2<true>,
                             cudaFuncAttributeMaxDynamicSharedMemorySize, AGG2_SMEM);
        cudaFuncSetAttribute(agg_tc<DOUT, 256, false>,
                             cudaFuncAttributeMaxDynamicSharedMemorySize, AGG_SMEM_64);
        attr_set = 1;
    }

    // ---- layer 0 ----
    gemm_tc<<<dim3(HD / 128, NN / 128, BC), t256, GEMM_SMEM>>>(x, W0, feat, FIN, HD,
                                                               (size_t)C * NN * FIN, 0);
    elr_kernel<<<BC * NN, 128>>>(feat, al0, ar0, el, er, DHID);
    agg_tc2<true><<<dim3(NN / 128, H, BC), t256, AGG2_SMEM>>>(adj, feat, el, er, b0, hbuf);

    // ---- layer 1 ----
    gemm_tc<<<dim3(HD / 128, NN / 128, BC), t256, GEMM_SMEM>>>(hbuf, W1, feat, HD, HD,
                                                               (size_t)C * NN * HD, (size_t)NN * HD);
    elr_kernel<<<BC * NN, 128>>>(feat, al1, ar1, el, er, DHID);
    agg_tc2<true><<<dim3(NN / 128, H, BC), t256, AGG2_SMEM>>>(adj, feat, el, er, b1, hbuf);

    // ---- layer 2 ----
    gemm_tc<<<dim3(HD2 / 128, NN / 128, BC), t256, GEMM_SMEM>>>(hbuf, W2, feat, HD, HD2,
                                                                (size_t)C * NN * HD, (size_t)NN * HD);
    elr_kernel<<<BC * NN, 128>>>(feat, al2, ar2, el, er, DOUT);
    agg_tc<DOUT, 256, false><<<dim3(NN / 256, H, BC), t256, AGG_SMEM_64>>>(adj, feat, el, er, b2, out2);

    // ---- head mean + concat ----
    mean_kernel<<<(B * NN * C * DOUT + 255) / 256, t256>>>(out2, out);
}

// round 9
// speedup vs baseline: 1.6963x; 1.1427x over previous
#include <cuda_runtime.h>
#include <cstdint>

// ---------------- problem constants ----------------
constexpr int B    = 8;
constexpr int C    = 5;
constexpr int NN   = 512;
constexpr int FIN  = 768;
constexpr int H    = 4;
constexpr int DHID = 128;
constexpr int DOUT = 64;
constexpr int HD   = H * DHID;   // 512
constexpr int HD2  = H * DOUT;   // 256
constexpr int BC   = B * C;      // 40

// ---------------- scratch ----------------
__device__ __align__(256) float g_feat[(size_t)BC * NN * HD];
__device__ __align__(256) float g_h   [(size_t)BC * NN * HD];
__device__ __align__(256) float g_out2[(size_t)BC * NN * HD2];
__device__ __align__(256) float g_el  [BC * H * NN];
__device__ __align__(256) float g_er  [BC * H * NN];

// ---------------- gemm smem geometry ----------------
constexpr int AP = 20;
constexpr int BP = 136;
constexpr int A_STG = 128 * AP;
constexpr int B_STG = 16 * BP;
constexpr int STG   = A_STG + B_STG;
constexpr int GEMM_SMEM = 3 * STG * 4;

__device__ __forceinline__ uint32_t f2tf32(float f) {
    uint32_t u;
    asm("cvt.rna.tf32.f32 %0, %1;" : "=r"(u) : "f"(f));
    return u;
}

__device__ __forceinline__ void mma_tf32(float* d, const uint32_t* a, const uint32_t* b) {
    asm volatile(
        "mma.sync.aligned.m16n8k8.row.col.f32.tf32.tf32.f32 "
        "{%0,%1,%2,%3}, {%4,%5,%6,%7}, {%8,%9}, {%0,%1,%2,%3};\n"
        : "+f"(d[0]), "+f"(d[1]), "+f"(d[2]), "+f"(d[3])
        : "r"(a[0]), "r"(a[1]), "r"(a[2]), "r"(a[3]), "r"(b[0]), "r"(b[1]));
}

__device__ __forceinline__ void cp16(uint32_t smem_dst, const float* gsrc) {
    asm volatile("cp.async.ca.shared.global [%0], [%1], 16;\n"
                 :: "r"(smem_dst), "l"(gsrc));
}

// ---------------- tf32 GEMM (R5-validated mainloop) + fused el/er epilogue ----------
// C[bc](512 x Nn) = A[bc](512 x K) @ W[c](K x Nn); afterwards each warp adds its
// partial dot(feat_row, a_l/a_r[head]) into g_el/g_er via atomics (g_el/g_er pre-zeroed).
__global__ __launch_bounds__(256, 2) void gemm_tc(
    const float* __restrict__ A, const float* __restrict__ W,
    float* __restrict__ Co, int K, int Nn, size_t aSB, size_t aSC,
    const float* __restrict__ al, const float* __restrict__ ar,
    float* __restrict__ elo, float* __restrict__ ero, int Dh) {
    extern __shared__ float sm[];

    int bc = blockIdx.z;
    int b  = bc / C, c = bc % C;
    const float* Ab = A + (size_t)b * aSB + (size_t)c * aSC;
    const float* Wc = W + (size_t)c * K * Nn;
    float*       Cb = Co + (size_t)bc * NN * Nn;

    int m0 = blockIdx.y * 128, n0 = blockIdx.x * 128;
    int tid  = threadIdx.x;
    int lane = tid & 31, warp = tid >> 5;
    int wm = warp & 1, wn = warp >> 1;
    int gr = lane >> 2, tg = lane & 3;

    uint32_t smem_base = (uint32_t)__cvta_generic_to_shared(sm);

    int am0 = tid >> 2,          akq = (tid & 3) * 4;
    int am1 = (tid + 256) >> 2;
    int bk0 = tid >> 5,          bnq = (tid & 31) * 4;
    int bk1 = (tid + 256) >> 5;

    auto issue_stage = [&](int st, int t) {
        uint32_t aB = smem_base + (st * STG) * 4;
        uint32_t bB = smem_base + (st * STG + A_STG) * 4;
        const float* Abt = Ab + (size_t)m0 * K + t * 16;
        cp16(aB + (am0 * AP + akq) * 4, Abt + (size_t)am0 * K + akq);
        cp16(aB + (am1 * AP + akq) * 4, Abt + (size_t)am1 * K + akq);
        const float* Wct = Wc + (size_t)(t * 16) * Nn + n0;
        cp16(bB + (bk0 * BP + bnq) * 4, Wct + (size_t)bk0 * Nn + bnq);
        cp16(bB + (bk1 * BP + bnq) * 4, Wct + (size_t)bk1 * Nn + bnq);
    };

    float acc[4][4][4] = {};

    auto compute_stage = [&](int st) {
        const float* As = sm + st * STG;
        const float* Bs = As + A_STG;
#pragma unroll
        for (int ks = 0; ks < 16; ks += 8) {
            int kA = ks + tg;
            uint32_t ah[4][4], al_[4][4], bh[4][2], bl[4][2];
#pragma unroll
            for (int mt = 0; mt < 4; mt++) {
                int m = wm * 64 + mt * 16 + gr;
                float v0 = As[m * AP + kA];
                float v1 = As[(m + 8) * AP + kA];
                float v2 = As[m * AP + kA + 4];
                float v3 = As[(m + 8) * AP + kA + 4];
                ah[mt][0] = f2tf32(v0); al_[mt][0] = f2tf32(v0 - __uint_as_float(ah[mt][0]));
                ah[mt][1] = f2tf32(v1); al_[mt][1] = f2tf32(v1 - __uint_as_float(ah[mt][1]));
                ah[mt][2] = f2tf32(v2); al_[mt][2] = f2tf32(v2 - __uint_as_float(ah[mt][2]));
                ah[mt][3] = f2tf32(v3); al_[mt][3] = f2tf32(v3 - __uint_as_float(ah[mt][3]));
            }
#pragma unroll
            for (int nt = 0; nt < 4; nt++) {
                int n = wn * 32 + nt * 8 + gr;
                float w0 = Bs[kA * BP + n];
                float w1 = Bs[(kA + 4) * BP + n];
                bh[nt][0] = f2tf32(w0); bl[nt][0] = f2tf32(w0 - __uint_as_float(bh[nt][0]));
                bh[nt][1] = f2tf32(w1); bl[nt][1] = f2tf32(w1 - __uint_as_float(bh[nt][1]));
            }
#pragma unroll
            for (int mt = 0; mt < 4; mt++)
#pragma unroll
                for (int nt = 0; nt < 4; nt++) {
                    mma_tf32(acc[mt][nt], ah[mt], bh[nt]);
                    mma_tf32(acc[mt][nt], al_[mt], bh[nt]);
                    mma_tf32(acc[mt][nt], ah[mt], bl[nt]);
                }
        }
    };

    int T = K / 16;
    issue_stage(0, 0);
    asm volatile("cp.async.commit_group;\n" ::);
    issue_stage(1, 1);
    asm volatile("cp.async.commit_group;\n" ::);

    for (int i = 0; i < T; i++) {
        asm volatile("cp.async.wait_group 1;\n" ::);
        __syncthreads();
        if (i + 2 < T) issue_stage((i + 2) % 3, i + 2);
        asm volatile("cp.async.commit_group;\n" ::);
        compute_stage(i % 3);
    }

    // ---- epilogue: store C + fused el/er partials ----
    // warp's 32-col span lies within one head: head = (n0 + wn*32) / Dh
    int head  = (n0 + wn * 32) / Dh;
    int dbase = n0 + wn * 32 - head * Dh;
    const float* alh = al + ((size_t)c * H + head) * Dh;
    const float* arh = ar + ((size_t)c * H + head) * Dh;
    float* elh = elo + ((size_t)bc * H + head) * NN;
    float* erh = ero + ((size_t)bc * H + head) * NN;

#pragma unroll
    for (int mt = 0; mt < 4; mt++) {
        float el0 = 0.f, el1 = 0.f, er0 = 0.f, er1 = 0.f;
#pragma unroll
        for (int nt = 0; nt < 4; nt++) {
            int row = m0 + wm * 64 + mt * 16 + gr;
            int col = n0 + wn * 32 + nt * 8 + tg * 2;
            *(float2*)(Cb + (size_t)row * Nn + col) =
                make_float2(acc[mt][nt][0], acc[mt][nt][1]);
            *(float2*)(Cb + (size_t)(row + 8) * Nn + col) =
                make_float2(acc[mt][nt][2], acc[mt][nt][3]);

            int d = dbase + nt * 8 + tg * 2;
            float a0 = alh[d], a1 = alh[d + 1];
            float r0 = arh[d], r1 = arh[d + 1];
            el0 += acc[mt][nt][0] * a0 + acc[mt][nt][1] * a1;
            el1 += acc[mt][nt][2] * a0 + acc[mt][nt][3] * a1;
            er0 += acc[mt][nt][0] * r0 + acc[mt][nt][1] * r1;
            er1 += acc[mt][nt][2] * r0 + acc[mt][nt][3] * r1;
        }
        // reduce over tg (lanes gr*4 + tg): butterfly within groups of 4
#pragma unroll
        for (int o = 1; o < 4; o <<= 1) {
            el0 += __shfl_xor_sync(0xffffffffu, el0, o);
            el1 += __shfl_xor_sync(0xffffffffu, el1, o);
            er0 += __shfl_xor_sync(0xffffffffu, er0, o);
            er1 += __shfl_xor_sync(0xffffffffu, er1, o);
        }
        if (tg == 0) {
            int row = m0 + wm * 64 + mt * 16 + gr;
            atomicAdd(elh + row,     el0);
            atomicAdd(elh + row + 8, el1);
            atomicAdd(erh + row,     er0);
            atomicAdd(erh + row + 8, er1);
        }
    }
}

// ================= agg v2 (D=128, JT=128): produce-ahead, p 2-term split =================
template <bool RELU>
__global__ __launch_bounds__(256, 2) void agg_tc2(
    const float* __restrict__ adj,
    const float* __restrict__ feat,
    const float* __restrict__ el,
    const float* __restrict__ er,
    const float* __restrict__ bias,
    float* __restrict__ out) {
    constexpr int D  = 128, JT = 128;
    constexpr int PP = JT + 8;
    constexpr int FP = D + 8;
    constexpr int NSUB = 256 / JT;
    constexpr int ADJ_ST = 16 * JT;
    constexpr int F_ST   = 16 * FP;
    constexpr int P_ST   = 16 * PP;
    constexpr int T = NN / 16;

    extern __shared__ float sm[];
    float* el_s  = sm;
    float* er_s  = el_s + NN;
    float* m_s   = er_s + JT;
    float* sc_s  = m_s + JT;
    float* red   = sc_s + JT;
    float* s_red = red + 8;
    float* adj_s = s_red + NSUB * JT;
    float* f_s   = adj_s + 4 * ADJ_ST;
    float* p_s   = f_s + 4 * F_ST;

    int bc = blockIdx.z, h = blockIdx.y;
    int c = bc % C;
    int j0 = blockIdx.x * JT;
    int tid = threadIdx.x;
    int lane = tid & 31, warp = tid >> 5;
    int jm = warp & 1, dn = warp >> 1;
    int gr = lane >> 2, tg = lane & 3;

    const float* adj_bc = adj + (size_t)bc * NN * NN;
    const float* elh = el + (size_t)(bc * H + h) * NN;
    const float* erh = er + (size_t)(bc * H + h) * NN;
    const float* featb = feat + (size_t)bc * NN * (H * D) + h * D;

    uint32_t smem_u32 = (uint32_t)__cvta_generic_to_shared(sm);
    uint32_t adj_u32  = smem_u32 + (uint32_t)((adj_s - sm) * 4);
    uint32_t f_u32    = smem_u32 + (uint32_t)((f_s - sm) * 4);

    auto issue_stage = [&](int st, int t) {
        uint32_t aB = adj_u32 + st * ADJ_ST * 4;
#pragma unroll
        for (int l = 0; l < (16 * JT / 4) / 256; l++) {
            int s = tid + l * 256;
            int r = s / (JT / 4), cq = s % (JT / 4);
            cp16(aB + (r * JT + cq * 4) * 4,
                 adj_bc + (size_t)(t * 16 + r) * NN + j0 + cq * 4);
        }
        uint32_t fB = f_u32 + st * F_ST * 4;
#pragma unroll
        for (int l = 0; l < (16 * D / 4) / 256; l++) {
            int s = tid + l * 256;
            int r = s / (D / 4), cq = s % (D / 4);
            cp16(fB + (r * FP + cq * 4) * 4,
                 featb + (size_t)(t * 16 + r) * (H * D) + cq * 4);
        }
    };

    float e0 = elh[tid], e1 = elh[tid + 256];
    el_s[tid] = e0; el_s[tid + 256] = e1;
    if (tid < JT) er_s[tid] = erh[j0 + tid];

    issue_stage(0, 0);
    asm volatile("cp.async.commit_group;\n" ::);
    issue_stage(1, 1);
    asm volatile("cp.async.commit_group;\n" ::);
    issue_stage(2, 2);
    asm volatile("cp.async.commit_group;\n" ::);

    float v = fmaxf(e0, e1);
#pragma unroll
    for (int o = 16; o; o >>= 1) v = fmaxf(v, __shfl_xor_sync(0xffffffffu, v, o));
    if (lane == 0) red[warp] = v;
    __syncthreads();
    if (tid == 0) {
        float m = red[0];
#pragma unroll
        for (int w = 1; w < 8; w++) m = fmaxf(m, red[w]);
        red[0] = m;
    }
    __syncthreads();
    if (tid < JT) {
        float e = red[0] + er_s[tid];
        m_s[tid] = e > 0.f ? e : 0.2f * e;
    }

    int pj  = tid % JT;
    int pi0 = tid / JT;
    float s_priv = 0.f;

    auto produce = [&](int t) {
        const float* a_st = adj_s + (t % 4) * ADJ_ST;
        float* p_nb = p_s + (t & 1) * P_ST;
#pragma unroll
        for (int q = 0; q < 16 / NSUB; q++) {
            int r = pi0 + q * NSUB;
            float a = a_st[r * JT + pj];
            float p = 0.f;
            if (a > 0.f) {
                float e = el_s[t * 16 + r] + er_s[pj];
                e = e > 0.f ? e : 0.2f * e;
                p = __expf(e - m_s[pj]);
                s_priv += p;
            }
            p_nb[r * PP + pj] = p;
        }
    };

    asm volatile("cp.async.wait_group 2;\n" ::);
    __syncthreads();
    produce(0);

    float acc[4][4][4] = {};

    for (int i = 0; i < T; i++) {
        asm volatile("cp.async.wait_group 1;\n" ::);
        __syncthreads();

        const float* f_st  = f_s + (i % 4) * F_ST;
        const float* p_buf = p_s + (i & 1) * P_ST;
#pragma unroll
        for (int ks = 0; ks < 16; ks += 8) {
            int kA = ks + tg;
            uint32_t ah[4][4];     // p in tf32 (2-term split: p rounds, feat exact)
#pragma unroll
            for (int mt = 0; mt < 4; mt++) {
                int jb = jm * 64 + mt * 16 + gr;
                ah[mt][0] = f2tf32(p_buf[kA * PP + jb]);
                ah[mt][1] = f2tf32(p_buf[kA * PP + jb + 8]);
                ah[mt][2] = f2tf32(p_buf[(kA + 4) * PP + jb]);
                ah[mt][3] = f2tf32(p_buf[(kA + 4) * PP + jb + 8]);
            }
#pragma unroll
            for (int nt = 0; nt < 4; nt++) {
                int db = dn * 32 + nt * 8 + gr;
                float w0 = f_st[kA * FP + db];
                float w1 = f_st[(kA + 4) * FP + db];
                uint32_t bh[2], bl[2];
                bh[0] = f2tf32(w0); bl[0] = f2tf32(w0 - __uint_as_float(bh[0]));
                bh[1] = f2tf32(w1); bl[1] = f2tf32(w1 - __uint_as_float(bh[1]));
#pragma unroll
                for (int mt = 0; mt < 4; mt++) {
                    mma_tf32(acc[mt][nt], ah[mt], bh);
                    mma_tf32(acc[mt][nt], ah[mt], bl);
                }
            }
        }

        if (i + 1 < T) produce(i + 1);

        if (i + 3 < T) issue_stage((i + 3) % 4, i + 3);
        asm volatile("cp.async.commit_group;\n" ::);
    }

    s_red[pi0 * JT + pj] = s_priv;
    __syncthreads();
    if (tid < JT)
        sc_s[tid] = 1.0f / fmaxf(s_red[tid] + s_red[JT + tid], 1e-9f);
    __syncthreads();

    const float* bh_ = bias + (size_t)c * (H * D) + h * D;
#pragma unroll
    for (int mt = 0; mt < 4; mt++) {
#pragma unroll
        for (int nt = 0; nt < 4; nt++) {
            int jl = jm * 64 + mt * 16 + gr;
            int d  = dn * 32 + nt * 8 + tg * 2;
            float bb0 = bh_[d], bb1 = bh_[d + 1];
            float sc0 = sc_s[jl], sc1 = sc_s[jl + 8];
            float o0 = acc[mt][nt][0] * sc0 + bb0;
            float o1 = acc[mt][nt][1] * sc0 + bb1;
            float o2 = acc[mt][nt][2] * sc1 + bb0;
            float o3 = acc[mt][nt][3] * sc1 + bb1;
            if (RELU) {
                o0 = fmaxf(o0, 0.f); o1 = fmaxf(o1, 0.f);
                o2 = fmaxf(o2, 0.f); o3 = fmaxf(o3, 0.f);
            }
            int j = j0 + jl;
            *(float2*)(out + ((size_t)bc * NN + j) * (H * D) + h * D + d)     = make_float2(o0, o1);
            *(float2*)(out + ((size_t)bc * NN + j + 8) * (H * D) + h * D + d) = make_float2(o2, o3);
        }
    }
}

constexpr int AGG2_SMEM = (NN + 3 * 128 + 8 + 2 * 128 + 4 * 16 * 128 + 4 * 16 * 136 + 2 * 16 * 136) * 4;

// ================= agg v1 (layer 2: D=64, JT=256), p 2-term split =================
template <int D, int JT, bool RELU>
__global__ __launch_bounds__(256) void agg_tc(
    const float* __restrict__ adj,
    const float* __restrict__ feat,
    const float* __restrict__ el,
    const float* __restrict__ er,
    const float* __restrict__ bias,
    float* __restrict__ out) {
    constexpr int PP = JT + 8;
    constexpr int FP = D + 8;
    constexpr int WJ = JT / 64;
    constexpr int NSUB = 256 / JT;
    constexpr int ADJ_ST = 16 * JT;
    constexpr int F_ST   = 16 * FP;
    constexpr int P_ST   = 16 * PP;

    extern __shared__ float sm[];
    float* el_s  = sm;
    float* er_s  = el_s + NN;
    float* m_s   = er_s + JT;
    float* sc_s  = m_s + JT;
    float* red   = sc_s + JT;
    float* s_red = red + 8;
    float* adj_s = s_red + NSUB * JT;
    float* f_s   = adj_s + 3 * ADJ_ST;
    float* p_s   = f_s + 3 * F_ST;

    int bc = blockIdx.z, h = blockIdx.y;
    int c = bc % C;
    int j0 = blockIdx.x * JT;
    int tid = threadIdx.x;
    int lane = tid & 31, warp = tid >> 5;
    int jm = warp % WJ, dn = warp / WJ;
    int gr = lane >> 2, tg = lane & 3;

    const float* adj_bc = adj + (size_t)bc * NN * NN;
    const float* elh = el + (size_t)(bc * H + h) * NN;
    const float* erh = er + (size_t)(bc * H + h) * NN;
    const float* featb = feat + (size_t)bc * NN * (H * D) + h * D;

    uint32_t smem_u32 = (uint32_t)__cvta_generic_to_shared(sm);
    uint32_t adj_u32  = smem_u32 + (uint32_t)((adj_s - sm) * 4);
    uint32_t f_u32    = smem_u32 + (uint32_t)((f_s - sm) * 4);

    auto issue_stage = [&](int st, int t) {
        uint32_t aB = adj_u32 + st * ADJ_ST * 4;
#pragma unroll
        for (int l = 0; l < (16 * JT / 4) / 256; l++) {
            int s = tid + l * 256;
            int r = s / (JT / 4), cq = s % (JT / 4);
            cp16(aB + (r * JT + cq * 4) * 4,
                 adj_bc + (size_t)(t * 16 + r) * NN + j0 + cq * 4);
        }
        uint32_t fB = f_u32 + st * F_ST * 4;
#pragma unroll
        for (int l = 0; l < (16 * D / 4) / 256; l++) {
            int s = tid + l * 256;
            int r = s / (D / 4), cq = s % (D / 4);
            cp16(fB + (r * FP + cq * 4) * 4,
                 featb + (size_t)(t * 16 + r) * (H * D) + cq * 4);
        }
    };

    float e0 = elh[tid], e1 = elh[tid + 256];
    el_s[tid] = e0; el_s[tid + 256] = e1;
#pragma unroll
    for (int t = tid; t < JT; t += 256) er_s[t] = erh[j0 + t];

    issue_stage(0, 0);
    asm volatile("cp.async.commit_group;\n" ::);
    issue_stage(1, 1);
    asm volatile("cp.async.commit_group;\n" ::);

    float v = fmaxf(e0, e1);
#pragma unroll
    for (int o = 16; o; o >>= 1) v = fmaxf(v, __shfl_xor_sync(0xffffffffu, v, o));
    if (lane == 0) red[warp] = v;
    __syncthreads();
    if (tid == 0) {
        float m = red[0];
#pragma unroll
        for (int w = 1; w < 8; w++) m = fmaxf(m, red[w]);
        red[0] = m;
    }
    __syncthreads();
#pragma unroll
    for (int t = tid; t < JT; t += 256) {
        float e = red[0] + er_s[t];
        m_s[t] = e > 0.f ? e : 0.2f * e;
    }

    int pj  = tid % JT;
    int pi0 = tid / JT;

    float acc[4][4][4] = {};
    float s_priv = 0.f;

    constexpr int T = NN / 16;
    for (int i = 0; i < T; i++) {
        asm volatile("cp.async.wait_group 1;\n" ::);
        __syncthreads();

        const float* a_st = adj_s + (i % 3) * ADJ_ST;
        float* p_buf = p_s + (i & 1) * P_ST;
#pragma unroll
        for (int q = 0; q < 16 / NSUB; q++) {
            int r = pi0 + q * NSUB;
            float a = a_st[r * JT + pj];
            float p = 0.f;
            if (a > 0.f) {
                float e = el_s[i * 16 + r] + er_s[pj];
                e = e > 0.f ? e : 0.2f * e;
                p = __expf(e - m_s[pj]);
                s_priv += p;
            }
            p_buf[r * PP + pj] = p;
        }
        __syncthreads();

        const float* f_st = f_s + (i % 3) * F_ST;
#pragma unroll
        for (int ks = 0; ks < 16; ks += 8) {
            int kA = ks + tg;
            uint32_t ah[4][4];
#pragma unroll
            for (int mt = 0; mt < 4; mt++) {
                int jb = jm * 64 + mt * 16 + gr;
                ah[mt][0] = f2tf32(p_buf[kA * PP + jb]);
                ah[mt][1] = f2tf32(p_buf[kA * PP + jb + 8]);
                ah[mt][2] = f2tf32(p_buf[(kA + 4) * PP + jb]);
                ah[mt][3] = f2tf32(p_buf[(kA + 4) * PP + jb + 8]);
            }
#pragma unroll
            for (int nt = 0; nt < 4; nt++) {
                int db = dn * 32 + nt * 8 + gr;
                float w0 = f_st[kA * FP + db];
                float w1 = f_st[(kA + 4) * FP + db];
                uint32_t bh[2], bl[2];
                bh[0] = f2tf32(w0); bl[0] = f2tf32(w0 - __uint_as_float(bh[0]));
                bh[1] = f2tf32(w1); bl[1] = f2tf32(w1 - __uint_as_float(bh[1]));
#pragma unroll
                for (int mt = 0; mt < 4; mt++) {
                    mma_tf32(acc[mt][nt], ah[mt], bh);
                    mma_tf32(acc[mt][nt], ah[mt], bl);
                }
            }
        }

        if (i + 2 < T) issue_stage((i + 2) % 3, i + 2);
        asm volatile("cp.async.commit_group;\n" ::);
    }

    s_red[pi0 * JT + pj] = s_priv;
    __syncthreads();
#pragma unroll
    for (int t = tid; t < JT; t += 256) {
        float sv = s_red[t];
        if (NSUB == 2) sv += s_red[JT + t];
        sc_s[t] = 1.0f / fmaxf(sv, 1e-9f);
    }
    __syncthreads();

    const float* bh_ = bias + (size_t)c * (H * D) + h * D;
#pragma unroll
    for (int mt = 0; mt < 4; mt++) {
#pragma unroll
        for (int nt = 0; nt < 4; nt++) {
            int jl = jm * 64 + mt * 16 + gr;
            int d  = dn * 32 + nt * 8 + tg * 2;
            float bb0 = bh_[d], bb1 = bh_[d + 1];
            float sc0 = sc_s[jl], sc1 = sc_s[jl + 8];
            float o0 = acc[mt][nt][0] * sc0 + bb0;
            float o1 = acc[mt][nt][1] * sc0 + bb1;
            float o2 = acc[mt][nt][2] * sc1 + bb0;
            float o3 = acc[mt][nt][3] * sc1 + bb1;
            if (RELU) {
                o0 = fmaxf(o0, 0.f); o1 = fmaxf(o1, 0.f);
                o2 = fmaxf(o2, 0.f); o3 = fmaxf(o3, 0.f);
            }
            int j = j0 + jl;
            *(float2*)(out + ((size_t)bc * NN + j) * (H * D) + h * D + d)     = make_float2(o0, o1);
            *(float2*)(out + ((size_t)bc * NN + j + 8) * (H * D) + h * D + d) = make_float2(o2, o3);
        }
    }
}

constexpr int agg_smem_bytes(int D, int JT) {
    int FP = D + 8, PP = JT + 8, NSUB = 256 / JT;
    return (NN + 3 * JT + 8 + NSUB * JT + 3 * 16 * JT + 3 * 16 * FP + 2 * 16 * PP) * 4;
}
constexpr int AGG_SMEM_64 = agg_smem_bytes(64, 256);

// ---------------- head-mean + channel concat ----------------
__global__ void mean_kernel(const float* __restrict__ in2, float* __restrict__ out) {
    int idx = blockIdx.x * 256 + threadIdx.x;
    if (idx >= B * NN * C * DOUT) return;
    int d = idx % DOUT;
    int c = (idx / DOUT) % C;
    int n = (idx / (DOUT * C)) % NN;
    int b = idx / (DOUT * C * NN);
    const float* p = in2 + ((size_t)(b * C + c) * NN + n) * HD2 + d;
    out[idx] = 0.25f * (p[0] + p[DOUT] + p[2 * DOUT] + p[3 * DOUT]);
}

// ---------------- launch ----------------
extern "C" void kernel_launch(void* const* d_in, const int* in_sizes, int n_in,
                              void* d_out, int out_size) {
    const float* x   = (const float*)d_in[0];
    const float* adj = (const float*)d_in[1];
    const float* W0  = (const float*)d_in[2];
    const float* al0 = (const float*)d_in[3];
    const float* ar0 = (const float*)d_in[4];
    const float* b0  = (const float*)d_in[5];
    const float* W1  = (const float*)d_in[6];
    const float* al1 = (const float*)d_in[7];
    const float* ar1 = (const float*)d_in[8];
    const float* b1  = (const float*)d_in[9];
    const float* W2  = (const float*)d_in[10];
    const float* al2 = (const float*)d_in[11];
    const float* ar2 = (const float*)d_in[12];
    const float* b2  = (const float*)d_in[13];
    float* out = (float*)d_out;

    float *feat, *hbuf, *el, *er, *out2;
    cudaGetSymbolAddress((void**)&feat, g_feat);
    cudaGetSymbolAddress((void**)&hbuf, g_h);
    cudaGetSymbolAddress((void**)&el,   g_el);
    cudaGetSymbolAddress((void**)&er,   g_er);
    cudaGetSymbolAddress((void**)&out2, g_out2);

    dim3 t256(256);
    static int attr_set = 0;
    if (!attr_set) {
        cudaFuncSetAttribute(gemm_tc, cudaFuncAttributeMaxDynamicSharedMemorySize, GEMM_SMEM);
        cudaFuncSetAttribute(agg_tc2<true>,
                             cudaFuncAttributeMaxDynamicSharedMemorySize, AGG2_SMEM);
        cudaFuncSetAttribute(agg_tc<DOUT, 256, false>,
                             cudaFuncAttributeMaxDynamicSharedMemorySize, AGG_SMEM_64);
        attr_set = 1;
    }

    size_t elr_bytes = (size_t)BC * H * NN * sizeof(float);

    // ---- layer 0 ----
    cudaMemsetAsync(el, 0, elr_bytes);
    cudaMemsetAsync(er, 0, elr_bytes);
    gemm_tc<<<dim3(HD / 128, NN / 128, BC), t256, GEMM_SMEM>>>(
        x, W0, feat, FIN, HD, (size_t)C * NN * FIN, 0, al0, ar0, el, er, DHID);
    agg_tc2<true><<<dim3(NN / 128, H, BC), t256, AGG2_SMEM>>>(adj, feat, el, er, b0, hbuf);

    // ---- layer 1 ----
    cudaMemsetAsync(el, 0, elr_bytes);
    cudaMemsetAsync(er, 0, elr_bytes);
    gemm_tc<<<dim3(HD / 128, NN / 128, BC), t256, GEMM_SMEM>>>(
        hbuf, W1, feat, HD, HD, (size_t)C * NN * HD, (size_t)NN * HD, al1, ar1, el, er, DHID);
    agg_tc2<true><<<dim3(NN / 128, H, BC), t256, AGG2_SMEM>>>(adj, feat, el, er, b1, hbuf);

    // ---- layer 2 ----
    cudaMemsetAsync(el, 0, elr_bytes);
    cudaMemsetAsync(er, 0, elr_bytes);
    gemm_tc<<<dim3(HD2 / 128, NN / 128, BC), t256, GEMM_SMEM>>>(
        hbuf, W2, feat, HD, HD2, (size_t)C * NN * HD, (size_t)NN * HD, al2, ar2, el, er, DOUT);
    agg_tc<DOUT, 256, false><<<dim3(NN / 256, H, BC), t256, AGG_SMEM_64>>>(adj, feat, el, er, b2, out2);

    // ---- head mean + concat ----
    mean_kernel<<<(B * NN * C * DOUT + 255) / 256, t256>>>(out2, out);
}